// round 2
// baseline (speedup 1.0000x reference)
#include <cuda_runtime.h>
#include <math.h>

#define BB 8
#define CINN 3
#define DM 512
#define N2C 32
#define NLAY 4
#define LL 4096
#define LAT 256

// ---------------- scratch (device globals; no allocation allowed) -------------
__device__ float g_h[BB * DM * LL];      // 64 MB  activations, layout [b][d][l]
__device__ float g_y[BB * DM * LL];      // 64 MB  gelu(ssm) output, layout [b][d][l]
__device__ float g_wre[NLAY * DM * N2C];
__device__ float g_wim[NLAY * DM * N2C];
__device__ float g_cre[NLAY * DM * N2C]; // holds 2*Re(Cc)
__device__ float g_cim[NLAY * DM * N2C]; // holds 2*Im(Cc)
__device__ float g_hbar[BB * DM];

// ---------------- kernel 0: per-layer SSM parameter precompute ----------------
__global__ void precompute_kernel(const float* __restrict__ log_dt,
                                  const float* __restrict__ log_A_real,
                                  const float* __restrict__ A_imag,
                                  const float* __restrict__ C_re,
                                  const float* __restrict__ C_im)
{
    int idx = blockIdx.x * blockDim.x + threadIdx.x;   // layer*DM*N2 + d*N2 + n
    if (idx >= NLAY * DM * N2C) return;
    int hd = idx / N2C;            // layer*DM + d
    float dt  = expf(log_dt[hd]);
    float are = -expf(log_A_real[idx]);
    float aim = A_imag[idx];
    float dre = are * dt;
    float dim = aim * dt;
    float er  = expf(dre);
    float wre = er * cosf(dim);
    float wim = er * sinf(dim);
    // E = exp(dtA) - 1
    float Ere = wre - 1.0f;
    float Eim = wim;
    // E / A  = E * conj(A) / |A|^2
    float den = are * are + aim * aim;
    float inv = 1.0f / den;
    float fre = (Ere * are + Eim * aim) * inv;
    float fim = (Eim * are - Ere * aim) * inv;
    // Cc = (C_re + i C_im) * (fre + i fim), store 2*Cc
    float crr = C_re[idx], cii = C_im[idx];
    float cre = crr * fre - cii * fim;
    float cim = crr * fim + cii * fre;
    g_wre[idx] = wre;
    g_wim[idx] = wim;
    g_cre[idx] = 2.0f * cre;
    g_cim[idx] = 2.0f * cim;
}

// ---------------- kernel 1: input projection + positional embedding ----------
__global__ void proj_kernel(const float* __restrict__ x,
                            const float* __restrict__ Wproj,
                            const float* __restrict__ bproj,
                            const float* __restrict__ pos)
{
    int idx = blockIdx.x * blockDim.x + threadIdx.x;   // b*DM*LL + d*LL + l
    if (idx >= BB * DM * LL) return;
    int l = idx & (LL - 1);
    int d = (idx >> 12) & (DM - 1);
    int b = idx >> 21;
    const float* xb = x + (size_t)b * CINN * LL;
    float v = bproj[d];
    v = fmaf(Wproj[d * 3 + 0], xb[l], v);
    v = fmaf(Wproj[d * 3 + 1], xb[LL + l], v);
    v = fmaf(Wproj[d * 3 + 2], xb[2 * LL + l], v);
    v += pos[(size_t)l * DM + d];
    g_h[idx] = v;
}

// ---------------- kernel 2: S4D scan + Dskip + exact GELU ---------------------
// warp handles 4 channels; 8 lanes per channel, 4 complex states per lane.
__global__ void scan_kernel(const float* __restrict__ Dskip, int layer)
{
    int tid  = blockIdx.x * blockDim.x + threadIdx.x;
    int warp = tid >> 5;
    int lane = tid & 31;
    int g = lane >> 3;          // channel group within warp
    int r = lane & 7;           // lane within group
    int ch = warp * 4 + g;      // b*DM + d
    if (ch >= BB * DM) return;
    int d = ch & (DM - 1);

    const float* u = g_h + (size_t)ch * LL;
    float* yo      = g_y + (size_t)ch * LL;

    int pbase = (layer * DM + d) * N2C + 4 * r;
    float wre[4], wim[4], cre[4], cim[4];
#pragma unroll
    for (int q = 0; q < 4; q++) {
        wre[q] = g_wre[pbase + q];
        wim[q] = g_wim[pbase + q];
        cre[q] = g_cre[pbase + q];
        cim[q] = g_cim[pbase + q];
    }
    float dsk = Dskip[layer * DM + d];

    float sre[4] = {0.f, 0.f, 0.f, 0.f};
    float sim[4] = {0.f, 0.f, 0.f, 0.f};

    for (int base = 0; base < LL; base += 32) {
        float uv[4];
#pragma unroll
        for (int k = 0; k < 4; k++) uv[k] = u[base + r + 8 * k];
        float yr[4] = {0.f, 0.f, 0.f, 0.f};
#pragma unroll
        for (int j = 0; j < 32; j++) {
            float uu = __shfl_sync(0xffffffffu, uv[j >> 3], (j & 7), 8);
            float c = 0.f;
#pragma unroll
            for (int q = 0; q < 4; q++) {
                float nre = fmaf(wre[q], sre[q], fmaf(-wim[q], sim[q], uu));
                float nim = fmaf(wre[q], sim[q], wim[q] * sre[q]);
                sre[q] = nre;
                sim[q] = nim;
                c = fmaf(cre[q], nre, c);
                c = fmaf(-cim[q], nim, c);
            }
            // reduce over the 8 lanes of this channel group
            c += __shfl_xor_sync(0xffffffffu, c, 4);
            c += __shfl_xor_sync(0xffffffffu, c, 2);
            c += __shfl_xor_sync(0xffffffffu, c, 1);
            if (r == (j & 7)) yr[j >> 3] = c;
        }
#pragma unroll
        for (int k = 0; k < 4; k++) {
            float v = fmaf(dsk, uv[k], yr[k]);
            float ge = 0.5f * v * (1.0f + erff(v * 0.70710678118654752f));
            yo[base + r + 8 * k] = ge;
        }
    }
}

// ---------------- kernel 3: Wout GEMM + GLU + residual ------------------------
// z[d,l] = (Wa[d,:]·y + bout[d]) * sigmoid(Wb[d,:]·y + bout[d+512]); h += z
#define GBM 64
#define GBN 128
#define GBK 16
__global__ void __launch_bounds__(256, 2)
gemm_glu_kernel(const float* __restrict__ Wout,
                const float* __restrict__ bout, int layer)
{
    __shared__ float As[GBK][GBM];
    __shared__ float Bs[GBK][GBM];
    __shared__ float Ys[GBK][GBN];

    int b  = blockIdx.z;
    int m0 = blockIdx.y * GBM;
    int n0 = blockIdx.x * GBN;

    const float* Wa = Wout + (size_t)layer * 2 * DM * DM;
    const float* Wb = Wa + (size_t)DM * DM;
    const float* Y  = g_y + (size_t)b * DM * LL;

    int tid = threadIdx.x;
    int tx = tid & 15;
    int ty = tid >> 4;

    float acc1[4][8];
    float acc2[4][8];
#pragma unroll
    for (int i = 0; i < 4; i++)
#pragma unroll
        for (int j = 0; j < 8; j++) { acc1[i][j] = 0.f; acc2[i][j] = 0.f; }

    int wrow = tid >> 2;            // 0..63
    int wk4  = (tid & 3) * 4;       // k offset (0,4,8,12)
    int yrow = tid >> 5;            // 0..7
    int ycol = (tid & 31) * 4;

    for (int k0 = 0; k0 < DM; k0 += GBK) {
        float4 a4 = *(const float4*)(Wa + (size_t)(m0 + wrow) * DM + k0 + wk4);
        float4 b4 = *(const float4*)(Wb + (size_t)(m0 + wrow) * DM + k0 + wk4);
        As[wk4 + 0][wrow] = a4.x; As[wk4 + 1][wrow] = a4.y;
        As[wk4 + 2][wrow] = a4.z; As[wk4 + 3][wrow] = a4.w;
        Bs[wk4 + 0][wrow] = b4.x; Bs[wk4 + 1][wrow] = b4.y;
        Bs[wk4 + 2][wrow] = b4.z; Bs[wk4 + 3][wrow] = b4.w;
        *(float4*)&Ys[yrow][ycol]     = *(const float4*)(Y + (size_t)(k0 + yrow) * LL + n0 + ycol);
        *(float4*)&Ys[yrow + 8][ycol] = *(const float4*)(Y + (size_t)(k0 + yrow + 8) * LL + n0 + ycol);
        __syncthreads();

#pragma unroll
        for (int k = 0; k < GBK; k++) {
            float4 af = *(float4*)&As[k][ty * 4];
            float4 bf = *(float4*)&Bs[k][ty * 4];
            float4 y0 = *(float4*)&Ys[k][tx * 4];
            float4 y1 = *(float4*)&Ys[k][64 + tx * 4];
            float am[4] = {af.x, af.y, af.z, af.w};
            float bm[4] = {bf.x, bf.y, bf.z, bf.w};
            float yn[8] = {y0.x, y0.y, y0.z, y0.w, y1.x, y1.y, y1.z, y1.w};
#pragma unroll
            for (int mi = 0; mi < 4; mi++)
#pragma unroll
                for (int ni = 0; ni < 8; ni++) {
                    acc1[mi][ni] = fmaf(am[mi], yn[ni], acc1[mi][ni]);
                    acc2[mi][ni] = fmaf(bm[mi], yn[ni], acc2[mi][ni]);
                }
        }
        __syncthreads();
    }

    float* H = g_h + (size_t)b * DM * LL;
#pragma unroll
    for (int mi = 0; mi < 4; mi++) {
        int o = m0 + ty * 4 + mi;
        float b1 = bout[layer * 2 * DM + o];
        float b2 = bout[layer * 2 * DM + DM + o];
#pragma unroll
        for (int ni = 0; ni < 8; ni++) {
            int l = n0 + ((ni < 4) ? (tx * 4 + ni) : (64 + tx * 4 + ni - 4));
            float a  = acc1[mi][ni] + b1;
            float gt = acc2[mi][ni] + b2;
            float z  = a / (1.0f + expf(-gt));
            size_t idx = (size_t)o * LL + l;
            H[idx] = H[idx] + z;
        }
    }
}

// ---------------- kernel 4: LayerNorm over channel dim (in place) -------------
__global__ void ln_kernel(const float* __restrict__ ln_g,
                          const float* __restrict__ ln_b, int layer)
{
    int l = blockIdx.x * blockDim.x + threadIdx.x;   // 0..LL-1
    int b = blockIdx.y;
    const float* gv = ln_g + layer * DM;
    const float* bv = ln_b + layer * DM;
    float* H = g_h + (size_t)b * DM * LL + l;
    float s = 0.f, s2 = 0.f;
#pragma unroll 8
    for (int d = 0; d < DM; d++) {
        float v = H[(size_t)d * LL];
        s += v;
        s2 = fmaf(v, v, s2);
    }
    float mu  = s * (1.0f / DM);
    float var = s2 * (1.0f / DM) - mu * mu;
    float inv = rsqrtf(var + 1e-5f);
#pragma unroll 8
    for (int d = 0; d < DM; d++) {
        float v = H[(size_t)d * LL];
        H[(size_t)d * LL] = (v - mu) * inv * gv[d] + bv[d];
    }
}

// ---------------- kernel 5: mean over L ---------------------------------------
__global__ void mean_kernel()
{
    int ch = blockIdx.x;   // b*DM + d
    const float* H = g_h + (size_t)ch * LL;
    float s = 0.f;
    for (int l = threadIdx.x; l < LL; l += 128) s += H[l];
    __shared__ float sm[128];
    sm[threadIdx.x] = s;
    __syncthreads();
    for (int o = 64; o > 0; o >>= 1) {
        if (threadIdx.x < o) sm[threadIdx.x] += sm[threadIdx.x + o];
        __syncthreads();
    }
    if (threadIdx.x == 0) g_hbar[ch] = sm[0] * (1.0f / LL);
}

// ---------------- kernel 6: stats head + output layout ------------------------
__global__ void stats_kernel(const float* __restrict__ Wstats,
                             const float* __restrict__ bstats,
                             float* __restrict__ out)
{
    int idx = blockIdx.x * blockDim.x + threadIdx.x;  // b*(2*LAT) + o
    if (idx >= BB * 2 * LAT) return;
    int b = idx / (2 * LAT);
    int o = idx % (2 * LAT);
    const float* hb = g_hbar + b * DM;
    const float* w  = Wstats + (size_t)o * DM;
    float s = bstats[o];
#pragma unroll 8
    for (int d = 0; d < DM; d++) s = fmaf(hb[d], w[d], s);
    // tuple-flatten order: all of mu, then all of log_sig
    int pos = (o < LAT) ? (b * LAT + o) : (BB * LAT + b * LAT + (o - LAT));
    out[pos] = s;
}

// ---------------- launch ------------------------------------------------------
extern "C" void kernel_launch(void* const* d_in, const int* in_sizes, int n_in,
                              void* d_out, int out_size)
{
    const float* x          = (const float*)d_in[0];
    const float* Wproj      = (const float*)d_in[1];
    const float* bproj      = (const float*)d_in[2];
    const float* pos        = (const float*)d_in[3];
    const float* log_dt     = (const float*)d_in[4];
    const float* log_A_real = (const float*)d_in[5];
    const float* A_imag     = (const float*)d_in[6];
    const float* C_re       = (const float*)d_in[7];
    const float* C_im       = (const float*)d_in[8];
    const float* Dskip      = (const float*)d_in[9];
    const float* Wout       = (const float*)d_in[10];
    const float* bout       = (const float*)d_in[11];
    const float* ln_g       = (const float*)d_in[12];
    const float* ln_b       = (const float*)d_in[13];
    const float* Wstats     = (const float*)d_in[14];
    const float* bstats     = (const float*)d_in[15];
    float* out = (float*)d_out;

    precompute_kernel<<<(NLAY * DM * N2C) / 256, 256>>>(log_dt, log_A_real, A_imag, C_re, C_im);
    proj_kernel<<<(BB * DM * LL) / 256, 256>>>(x, Wproj, bproj, pos);

    for (int layer = 0; layer < NLAY; ++layer) {
        // 4096 channels, 4 per warp, 8 warps per block -> 128 blocks
        scan_kernel<<<128, 256>>>(Dskip, layer);
        dim3 ggrid(LL / GBN, DM / GBM, BB);
        gemm_glu_kernel<<<ggrid, 256>>>(Wout, bout, layer);
        dim3 lgrid(LL / 256, BB);
        ln_kernel<<<lgrid, 256>>>(ln_g, ln_b, layer);
    }

    mean_kernel<<<BB * DM, 128>>>();
    stats_kernel<<<(BB * 2 * LAT + 255) / 256, 256>>>(Wstats, bstats, out);
}

// round 4
// speedup vs baseline: 1.5655x; 1.5655x over previous
#include <cuda_runtime.h>
#include <cuda_bf16.h>
#include <math.h>
#include <stdint.h>

#define BB 8
#define CINN 3
#define DM 512
#define N2C 32
#define NLAY 4
#define LL 4096
#define LAT 256

// ---------------- scratch (device globals; no allocation allowed) -------------
__device__ float g_h[BB * DM * LL];      // activations [b][d][l]
__device__ float g_y[BB * DM * LL];      // gelu(ssm)   [b][d][l]
__device__ __nv_bfloat16 g_yth[BB * LL * DM];  // Y^T hi  [b][l][d]
__device__ __nv_bfloat16 g_ytl[BB * LL * DM];  // Y^T lo  [b][l][d]
__device__ __nv_bfloat16 g_wh[NLAY * 2 * DM * DM]; // W hi [layer][row 0..1023][d]
__device__ __nv_bfloat16 g_wl[NLAY * 2 * DM * DM]; // W lo
__device__ float g_wre[NLAY * DM * N2C];
__device__ float g_wim[NLAY * DM * N2C];
__device__ float g_cre[NLAY * DM * N2C];
__device__ float g_cim[NLAY * DM * N2C];
__device__ float g_hbar[BB * DM];

// ---------------- helpers -----------------------------------------------------
__device__ __forceinline__ uint32_t smem_u32(const void* p) {
    uint32_t a;
    asm("{ .reg .u64 t; cvta.to.shared.u64 t, %1; cvt.u32.u64 %0, t; }" : "=r"(a) : "l"(p));
    return a;
}
#define SW128(o) ((o) ^ (((o) >> 3) & 0x70))

#define LDMX4(r, addr) \
    asm volatile("ldmatrix.sync.aligned.m8n8.x4.shared.b16 {%0,%1,%2,%3}, [%4];" \
        : "=r"((r)[0]), "=r"((r)[1]), "=r"((r)[2]), "=r"((r)[3]) : "r"(addr))

#define MMA16816(c, a, b) \
    asm volatile("mma.sync.aligned.m16n8k16.row.col.f32.bf16.bf16.f32 " \
        "{%0,%1,%2,%3}, {%4,%5,%6,%7}, {%8,%9}, {%0,%1,%2,%3};" \
        : "+f"((c)[0]), "+f"((c)[1]), "+f"((c)[2]), "+f"((c)[3]) \
        : "r"((a)[0]), "r"((a)[1]), "r"((a)[2]), "r"((a)[3]), \
          "r"((b)[0]), "r"((b)[1]))

__device__ __forceinline__ void cpa16(uint32_t dst, const void* src) {
    asm volatile("cp.async.cg.shared.global [%0], [%1], 16;" :: "r"(dst), "l"(src));
}

// ---------------- kernel 0: per-layer SSM parameter precompute ----------------
__global__ void precompute_kernel(const float* __restrict__ log_dt,
                                  const float* __restrict__ log_A_real,
                                  const float* __restrict__ A_imag,
                                  const float* __restrict__ C_re,
                                  const float* __restrict__ C_im)
{
    int idx = blockIdx.x * blockDim.x + threadIdx.x;
    if (idx >= NLAY * DM * N2C) return;
    int hd = idx / N2C;
    float dt  = expf(log_dt[hd]);
    float are = -expf(log_A_real[idx]);
    float aim = A_imag[idx];
    float er  = expf(are * dt);
    float wre = er * cosf(aim * dt);
    float wim = er * sinf(aim * dt);
    float Ere = wre - 1.0f;
    float Eim = wim;
    float inv = 1.0f / (are * are + aim * aim);
    float fre = (Ere * are + Eim * aim) * inv;
    float fim = (Eim * are - Ere * aim) * inv;
    float crr = C_re[idx], cii = C_im[idx];
    g_wre[idx] = wre;
    g_wim[idx] = wim;
    g_cre[idx] = 2.0f * (crr * fre - cii * fim);
    g_cim[idx] = 2.0f * (crr * fim + cii * fre);
}

// ---------------- kernel 0b: bf16-split Wout ----------------------------------
__global__ void wsplit_kernel(const float* __restrict__ Wout)
{
    int idx = blockIdx.x * blockDim.x + threadIdx.x;
    if (idx >= NLAY * 2 * DM * DM) return;
    float v = Wout[idx];
    __nv_bfloat16 h = __float2bfloat16(v);
    g_wh[idx] = h;
    g_wl[idx] = __float2bfloat16(v - __bfloat162float(h));
}

// ---------------- kernel 1: input projection + positional embedding ----------
__global__ void proj_kernel(const float* __restrict__ x,
                            const float* __restrict__ Wproj,
                            const float* __restrict__ bproj,
                            const float* __restrict__ pos)
{
    int idx = blockIdx.x * blockDim.x + threadIdx.x;
    if (idx >= BB * DM * LL) return;
    int l = idx & (LL - 1);
    int d = (idx >> 12) & (DM - 1);
    int b = idx >> 21;
    const float* xb = x + (size_t)b * CINN * LL;
    float v = bproj[d];
    v = fmaf(Wproj[d * 3 + 0], xb[l], v);
    v = fmaf(Wproj[d * 3 + 1], xb[LL + l], v);
    v = fmaf(Wproj[d * 3 + 2], xb[2 * LL + l], v);
    v += pos[(size_t)l * DM + d];
    g_h[idx] = v;
}

// ---------------- kernel 2: S4D scan + Dskip + exact GELU ---------------------
__global__ void scan_kernel(const float* __restrict__ Dskip, int layer)
{
    int tid  = blockIdx.x * blockDim.x + threadIdx.x;
    int warp = tid >> 5;
    int lane = tid & 31;
    int g = lane >> 3;
    int r = lane & 7;
    int ch = warp * 4 + g;
    if (ch >= BB * DM) return;
    int d = ch & (DM - 1);

    const float* u = g_h + (size_t)ch * LL;
    float* yo      = g_y + (size_t)ch * LL;

    int pbase = (layer * DM + d) * N2C + 4 * r;
    float wre[4], wim[4], cre[4], cim[4];
#pragma unroll
    for (int q = 0; q < 4; q++) {
        wre[q] = g_wre[pbase + q];
        wim[q] = g_wim[pbase + q];
        cre[q] = g_cre[pbase + q];
        cim[q] = g_cim[pbase + q];
    }
    float dsk = Dskip[layer * DM + d];

    float sre[4] = {0.f, 0.f, 0.f, 0.f};
    float sim[4] = {0.f, 0.f, 0.f, 0.f};

    for (int base = 0; base < LL; base += 32) {
        float uv[4];
#pragma unroll
        for (int k = 0; k < 4; k++) uv[k] = u[base + r + 8 * k];
        float yr[4] = {0.f, 0.f, 0.f, 0.f};
#pragma unroll
        for (int j = 0; j < 32; j++) {
            float uu = __shfl_sync(0xffffffffu, uv[j >> 3], (j & 7), 8);
            float c = 0.f;
#pragma unroll
            for (int q = 0; q < 4; q++) {
                float nre = fmaf(wre[q], sre[q], fmaf(-wim[q], sim[q], uu));
                float nim = fmaf(wre[q], sim[q], wim[q] * sre[q]);
                sre[q] = nre;
                sim[q] = nim;
                c = fmaf(cre[q], nre, c);
                c = fmaf(-cim[q], nim, c);
            }
            c += __shfl_xor_sync(0xffffffffu, c, 4);
            c += __shfl_xor_sync(0xffffffffu, c, 2);
            c += __shfl_xor_sync(0xffffffffu, c, 1);
            if (r == (j & 7)) yr[j >> 3] = c;
        }
#pragma unroll
        for (int k = 0; k < 4; k++) {
            float v = fmaf(dsk, uv[k], yr[k]);
            float ge = 0.5f * v * (1.0f + erff(v * 0.70710678118654752f));
            yo[base + r + 8 * k] = ge;
        }
    }
}

// ---------------- kernel 2b: transpose + bf16 split of Y ----------------------
__global__ void tsplit_kernel()
{
    __shared__ float tile[32][33];
    int b  = blockIdx.z;
    int d0 = blockIdx.y * 32;
    int l0 = blockIdx.x * 32;
    int tx = threadIdx.x;
    int ty = threadIdx.y;
    const float* src = g_y + ((size_t)b * DM + d0) * LL + l0;
#pragma unroll
    for (int k = 0; k < 4; k++)
        tile[ty + 8 * k][tx] = src[(size_t)(ty + 8 * k) * LL + tx];
    __syncthreads();
    __nv_bfloat16* dh = g_yth + ((size_t)b * LL + l0) * DM + d0;
    __nv_bfloat16* dl = g_ytl + ((size_t)b * LL + l0) * DM + d0;
#pragma unroll
    for (int k = 0; k < 4; k++) {
        float v = tile[tx][ty + 8 * k];
        __nv_bfloat16 h = __float2bfloat16(v);
        dh[(size_t)(ty + 8 * k) * DM + tx] = h;
        dl[(size_t)(ty + 8 * k) * DM + tx] = __float2bfloat16(v - __bfloat162float(h));
    }
}

// ---------------- kernel 3: HMMA bf16-split GEMM + GLU + residual -------------
// CTA tile: 128 M-rows (64 a-rows [m0,m0+64) + 64 gate-rows [512+m0, ...))
//           x 128 N-cols (l) x K=512 in 8 stages of 64.
// Warps 2(M)x4(N): warp = 64 M-rows (32a+32g) x 32 N.
#define STAGE 65536
#define OFF_AH 0
#define OFF_AL 16384
#define OFF_BH 32768
#define OFF_BL 49152

__global__ void __launch_bounds__(256, 1)
gemm_mma_kernel(const float* __restrict__ bout, int layer)
{
    extern __shared__ char dsm[];
    uint32_t sb = smem_u32(dsm);

    const int tid  = threadIdx.x;
    const int wid  = tid >> 5;
    const int lane = tid & 31;
    const int wm   = wid >> 2;      // 0..1
    const int wn   = wid & 3;       // 0..3
    const int n0   = blockIdx.x * 128;
    const int m0   = blockIdx.y * 64;   // a-row base (gate = 512+m0)
    const int bb   = blockIdx.z;

    const __nv_bfloat16* Wh = g_wh + (size_t)layer * 2 * DM * DM;
    const __nv_bfloat16* Wl = g_wl + (size_t)layer * 2 * DM * DM;
    const __nv_bfloat16* Bh = g_yth + (size_t)bb * LL * DM;
    const __nv_bfloat16* Bl = g_ytl + (size_t)bb * LL * DM;

    // per-stage loader: 128 rows x 64 bf16 per tile, 4 tiles
    auto load_stage = [&](int c) {
        int buf = c & 1;
        int kb = c * 64;
        uint32_t base = sb + buf * STAGE;
#pragma unroll
        for (int i = 0; i < 4; i++) {
            int v = tid + (i << 8);
            int row = v >> 3;
            int seg = v & 7;
            uint32_t dsw = SW128((uint32_t)(row * 128 + seg * 16));
            int p = (row < 64) ? (m0 + row) : (448 + m0 + row); // 512+m0+(row-64)
            size_t ao = (size_t)p * DM + kb + seg * 8;
            cpa16(base + OFF_AH + dsw, Wh + ao);
            cpa16(base + OFF_AL + dsw, Wl + ao);
            size_t bo = (size_t)(n0 + row) * DM + kb + seg * 8;
            cpa16(base + OFF_BH + dsw, Bh + bo);
            cpa16(base + OFF_BL + dsw, Bl + bo);
        }
        asm volatile("cp.async.commit_group;" ::: "memory");
    };

    float acc[4][4][4];
#pragma unroll
    for (int i = 0; i < 4; i++)
#pragma unroll
        for (int j = 0; j < 4; j++)
#pragma unroll
            for (int k = 0; k < 4; k++) acc[i][j][k] = 0.f;

    load_stage(0);
    load_stage(1);

    for (int s = 0; s < 8; ++s) {
        if (s < 7) asm volatile("cp.async.wait_group 1;" ::: "memory");
        else       asm volatile("cp.async.wait_group 0;" ::: "memory");
        __syncthreads();

        uint32_t base = sb + (s & 1) * STAGE;
#pragma unroll
        for (int k16 = 0; k16 < 4; ++k16) {
            uint32_t ah[4][4], al[4][4], bhf[4][2], blf[4][2];
#pragma unroll
            for (int mf = 0; mf < 4; ++mf) {
                int rowbase = (mf < 2) ? (wm * 32 + mf * 16)
                                       : (64 + wm * 32 + (mf - 2) * 16);
                int row = rowbase + (lane & 15);
                uint32_t off = SW128((uint32_t)(row * 128 + k16 * 32 + ((lane >> 4) << 4)));
                LDMX4(ah[mf], base + OFF_AH + off);
                LDMX4(al[mf], base + OFF_AL + off);
            }
#pragma unroll
            for (int pr = 0; pr < 2; ++pr) {
                int row = wn * 32 + pr * 16 + (lane & 7) + ((lane >> 4) << 3);
                uint32_t off = SW128((uint32_t)(row * 128 + k16 * 32 + (((lane >> 3) & 1) << 4)));
                uint32_t t[4];
                LDMX4(t, base + OFF_BH + off);
                bhf[2 * pr][0] = t[0]; bhf[2 * pr][1] = t[1];
                bhf[2 * pr + 1][0] = t[2]; bhf[2 * pr + 1][1] = t[3];
                LDMX4(t, base + OFF_BL + off);
                blf[2 * pr][0] = t[0]; blf[2 * pr][1] = t[1];
                blf[2 * pr + 1][0] = t[2]; blf[2 * pr + 1][1] = t[3];
            }
#pragma unroll
            for (int mf = 0; mf < 4; ++mf)
#pragma unroll
                for (int nf = 0; nf < 4; ++nf) {
                    MMA16816(acc[mf][nf], ah[mf], bhf[nf]);
                    MMA16816(acc[mf][nf], al[mf], bhf[nf]);
                    MMA16816(acc[mf][nf], ah[mf], blf[nf]);
                }
        }
        __syncthreads();
        if (s < 6) load_stage(s + 2);
    }

    // epilogue: GLU + bias + residual, all in registers (a and gate co-located)
    const float* bo = bout + layer * 2 * DM;
    int groupid = lane >> 2;
    int tg = lane & 3;
#pragma unroll
    for (int mf = 0; mf < 2; ++mf) {
#pragma unroll
        for (int rp = 0; rp < 2; ++rp) {
            int o = m0 + wm * 32 + mf * 16 + groupid + rp * 8;
            float b1 = bo[o];
            float b2 = bo[DM + o];
            float* H = g_h + ((size_t)bb * DM + o) * LL + n0 + wn * 32;
#pragma unroll
            for (int nf = 0; nf < 4; ++nf) {
                float a0 = acc[mf][nf][rp * 2 + 0] + b1;
                float a1 = acc[mf][nf][rp * 2 + 1] + b1;
                float g0 = acc[mf + 2][nf][rp * 2 + 0] + b2;
                float g1 = acc[mf + 2][nf][rp * 2 + 1] + b2;
                float z0 = a0 / (1.0f + expf(-g0));
                float z1 = a1 / (1.0f + expf(-g1));
                float2* ptr = (float2*)(H + nf * 8 + tg * 2);
                float2 h2 = *ptr;
                h2.x += z0;
                h2.y += z1;
                *ptr = h2;
            }
        }
    }
}

// ---------------- kernel 4: LayerNorm over channel dim (in place) -------------
__global__ void ln_kernel(const float* __restrict__ ln_g,
                          const float* __restrict__ ln_b, int layer)
{
    int l = blockIdx.x * blockDim.x + threadIdx.x;
    int b = blockIdx.y;
    const float* gv = ln_g + layer * DM;
    const float* bv = ln_b + layer * DM;
    float* H = g_h + (size_t)b * DM * LL + l;
    float s = 0.f, s2 = 0.f;
#pragma unroll 8
    for (int d = 0; d < DM; d++) {
        float v = H[(size_t)d * LL];
        s += v;
        s2 = fmaf(v, v, s2);
    }
    float mu  = s * (1.0f / DM);
    float var = s2 * (1.0f / DM) - mu * mu;
    float inv = rsqrtf(var + 1e-5f);
#pragma unroll 8
    for (int d = 0; d < DM; d++) {
        float v = H[(size_t)d * LL];
        H[(size_t)d * LL] = (v - mu) * inv * gv[d] + bv[d];
    }
}

// ---------------- kernel 5: mean over L ---------------------------------------
__global__ void mean_kernel()
{
    int ch = blockIdx.x;
    const float* H = g_h + (size_t)ch * LL;
    float s = 0.f;
    for (int l = threadIdx.x; l < LL; l += 128) s += H[l];
    __shared__ float sm[128];
    sm[threadIdx.x] = s;
    __syncthreads();
    for (int o = 64; o > 0; o >>= 1) {
        if (threadIdx.x < o) sm[threadIdx.x] += sm[threadIdx.x + o];
        __syncthreads();
    }
    if (threadIdx.x == 0) g_hbar[ch] = sm[0] * (1.0f / LL);
}

// ---------------- kernel 6: stats head + output layout ------------------------
__global__ void stats_kernel(const float* __restrict__ Wstats,
                             const float* __restrict__ bstats,
                             float* __restrict__ out)
{
    int idx = blockIdx.x * blockDim.x + threadIdx.x;
    if (idx >= BB * 2 * LAT) return;
    int b = idx / (2 * LAT);
    int o = idx % (2 * LAT);
    const float* hb = g_hbar + b * DM;
    const float* w  = Wstats + (size_t)o * DM;
    float s = bstats[o];
#pragma unroll 8
    for (int d = 0; d < DM; d++) s = fmaf(hb[d], w[d], s);
    int pos = (o < LAT) ? (b * LAT + o) : (BB * LAT + b * LAT + (o - LAT));
    out[pos] = s;
}

// ---------------- launch ------------------------------------------------------
extern "C" void kernel_launch(void* const* d_in, const int* in_sizes, int n_in,
                              void* d_out, int out_size)
{
    const float* x          = (const float*)d_in[0];
    const float* Wproj      = (const float*)d_in[1];
    const float* bproj      = (const float*)d_in[2];
    const float* pos        = (const float*)d_in[3];
    const float* log_dt     = (const float*)d_in[4];
    const float* log_A_real = (const float*)d_in[5];
    const float* A_imag     = (const float*)d_in[6];
    const float* C_re       = (const float*)d_in[7];
    const float* C_im       = (const float*)d_in[8];
    const float* Dskip      = (const float*)d_in[9];
    const float* Wout       = (const float*)d_in[10];
    const float* bout       = (const float*)d_in[11];
    const float* ln_g       = (const float*)d_in[12];
    const float* ln_b       = (const float*)d_in[13];
    const float* Wstats     = (const float*)d_in[14];
    const float* bstats     = (const float*)d_in[15];
    float* out = (float*)d_out;

    const int gemm_smem = 2 * STAGE;   // 128 KB
    cudaFuncSetAttribute(gemm_mma_kernel,
                         cudaFuncAttributeMaxDynamicSharedMemorySize, gemm_smem);

    precompute_kernel<<<(NLAY * DM * N2C) / 256, 256>>>(log_dt, log_A_real, A_imag, C_re, C_im);
    wsplit_kernel<<<(NLAY * 2 * DM * DM) / 256, 256>>>(Wout);
    proj_kernel<<<(BB * DM * LL) / 256, 256>>>(x, Wproj, bproj, pos);

    for (int layer = 0; layer < NLAY; ++layer) {
        scan_kernel<<<128, 256>>>(Dskip, layer);
        dim3 tgrid(LL / 32, DM / 32, BB);
        tsplit_kernel<<<tgrid, dim3(32, 8)>>>();
        dim3 ggrid(LL / 128, DM / 64, BB);
        gemm_mma_kernel<<<ggrid, 256, gemm_smem>>>(bout, layer);
        dim3 lgrid(LL / 256, BB);
        ln_kernel<<<lgrid, 256>>>(ln_g, ln_b, layer);
    }

    mean_kernel<<<BB * DM, 128>>>();
    stats_kernel<<<(BB * 2 * LAT + 255) / 256, 256>>>(Wstats, bstats, out);
}

// round 7
// speedup vs baseline: 1.5962x; 1.0196x over previous
#include <cuda_runtime.h>
#include <cuda_bf16.h>
#include <math.h>
#include <stdint.h>

#define BB 8
#define CINN 3
#define DM 512
#define N2C 32
#define NLAY 4
#define LL 4096
#define LAT 256
#define NCH 16      // chunks per sequence
#define CH 256      // chunk length

// ---------------- scratch (device globals; no allocation allowed) -------------
__device__ float g_h[BB * DM * LL];              // activations [b][d][l]
__device__ __nv_bfloat16 g_yth[BB * LL * DM];    // Y^T hi  [b][l][d]
__device__ __nv_bfloat16 g_ytl[BB * LL * DM];    // Y^T lo  [b][l][d]
__device__ __nv_bfloat16 g_wh[NLAY * 2 * DM * DM];
__device__ __nv_bfloat16 g_wl[NLAY * 2 * DM * DM];
__device__ float g_wre[NLAY * DM * N2C];
__device__ float g_wim[NLAY * DM * N2C];
__device__ float g_cre[NLAY * DM * N2C];
__device__ float g_cim[NLAY * DM * N2C];
__device__ float g_wpre[NLAY * DM * N2C];        // w^CH real
__device__ float g_wpim[NLAY * DM * N2C];        // w^CH imag
__device__ float g_bnd[BB * DM * NCH * N2C * 2];   // chunk remainders r_c
__device__ float g_state[BB * DM * NCH * N2C * 2]; // incoming states S_c
__device__ float g_hbar[BB * DM];

// ---------------- helpers -----------------------------------------------------
__device__ __forceinline__ uint32_t smem_u32(const void* p) {
    uint32_t a;
    asm("{ .reg .u64 t; cvta.to.shared.u64 t, %1; cvt.u32.u64 %0, t; }" : "=r"(a) : "l"(p));
    return a;
}
#define SW128(o) ((o) ^ (((o) >> 3) & 0x70))

#define LDMX4(r, addr) \
    asm volatile("ldmatrix.sync.aligned.m8n8.x4.shared.b16 {%0,%1,%2,%3}, [%4];" \
        : "=r"((r)[0]), "=r"((r)[1]), "=r"((r)[2]), "=r"((r)[3]) : "r"(addr))

#define MMA16816(c, a, b) \
    asm volatile("mma.sync.aligned.m16n8k16.row.col.f32.bf16.bf16.f32 " \
        "{%0,%1,%2,%3}, {%4,%5,%6,%7}, {%8,%9}, {%0,%1,%2,%3};" \
        : "+f"((c)[0]), "+f"((c)[1]), "+f"((c)[2]), "+f"((c)[3]) \
        : "r"((a)[0]), "r"((a)[1]), "r"((a)[2]), "r"((a)[3]), \
          "r"((b)[0]), "r"((b)[1]))

__device__ __forceinline__ void cpa16(uint32_t dst, const void* src) {
    asm volatile("cp.async.cg.shared.global [%0], [%1], 16;" :: "r"(dst), "l"(src));
}

// ---------------- kernel 0: per-layer SSM parameter precompute ----------------
__global__ void precompute_kernel(const float* __restrict__ log_dt,
                                  const float* __restrict__ log_A_real,
                                  const float* __restrict__ A_imag,
                                  const float* __restrict__ C_re,
                                  const float* __restrict__ C_im)
{
    int idx = blockIdx.x * blockDim.x + threadIdx.x;
    if (idx >= NLAY * DM * N2C) return;
    int hd = idx / N2C;
    float dt  = expf(log_dt[hd]);
    float are = -expf(log_A_real[idx]);
    float aim = A_imag[idx];
    float dre = are * dt;
    float dim = aim * dt;
    float er  = expf(dre);
    float wre = er * cosf(dim);
    float wim = er * sinf(dim);
    float Ere = wre - 1.0f;
    float Eim = wim;
    float inv = 1.0f / (are * are + aim * aim);
    float fre = (Ere * are + Eim * aim) * inv;
    float fim = (Eim * are - Ere * aim) * inv;
    float crr = C_re[idx], cii = C_im[idx];
    g_wre[idx] = wre;
    g_wim[idx] = wim;
    g_cre[idx] = 2.0f * (crr * fre - cii * fim);
    g_cim[idx] = 2.0f * (crr * fim + cii * fre);
    // w^CH = exp(CH * dtA)
    float pr = expf((float)CH * dre);
    g_wpre[idx] = pr * cosf((float)CH * dim);
    g_wpim[idx] = pr * sinf((float)CH * dim);
}

// ---------------- kernel 0b: bf16-split Wout ----------------------------------
__global__ void wsplit_kernel(const float* __restrict__ Wout)
{
    int idx = blockIdx.x * blockDim.x + threadIdx.x;
    if (idx >= NLAY * 2 * DM * DM) return;
    float v = Wout[idx];
    __nv_bfloat16 h = __float2bfloat16(v);
    g_wh[idx] = h;
    g_wl[idx] = __float2bfloat16(v - __bfloat162float(h));
}

// ---------------- kernel 1: input projection + positional embedding ----------
__global__ void proj_kernel(const float* __restrict__ x,
                            const float* __restrict__ Wproj,
                            const float* __restrict__ bproj,
                            const float* __restrict__ pos)
{
    int idx = blockIdx.x * blockDim.x + threadIdx.x;
    if (idx >= BB * DM * LL) return;
    int l = idx & (LL - 1);
    int d = (idx >> 12) & (DM - 1);
    int b = idx >> 21;
    const float* xb = x + (size_t)b * CINN * LL;
    float v = bproj[d];
    v = fmaf(Wproj[d * 3 + 0], xb[l], v);
    v = fmaf(Wproj[d * 3 + 1], xb[LL + l], v);
    v = fmaf(Wproj[d * 3 + 2], xb[2 * LL + l], v);
    v += pos[(size_t)l * DM + d];
    g_h[idx] = v;
}

// ---------------- kernel 2a: chunk remainders (state-only scan, s0 = 0) -------
// 8 lanes per (channel, chunk) pair; 4 complex states per lane.
__global__ void scanA_kernel(int layer)
{
    int gtid = blockIdx.x * blockDim.x + threadIdx.x;
    int pair = gtid >> 3;               // (ch, chunk)
    int r    = gtid & 7;
    int ch    = pair >> 4;
    int chunk = pair & 15;
    int d = ch & (DM - 1);

    int pbase = (layer * DM + d) * N2C + 4 * r;
    float wre[4], wim[4];
#pragma unroll
    for (int q = 0; q < 4; q++) {
        wre[q] = g_wre[pbase + q];
        wim[q] = g_wim[pbase + q];
    }

    const float* u = g_h + (size_t)ch * LL + chunk * CH;
    float sre[4] = {0.f, 0.f, 0.f, 0.f};
    float sim[4] = {0.f, 0.f, 0.f, 0.f};

    for (int base = 0; base < CH; base += 32) {
        float uv[4];
#pragma unroll
        for (int k = 0; k < 4; k++) uv[k] = u[base + r + 8 * k];
#pragma unroll
        for (int j = 0; j < 32; j++) {
            float uu = __shfl_sync(0xffffffffu, uv[j >> 3], (j & 7), 8);
#pragma unroll
            for (int q = 0; q < 4; q++) {
                float nre = fmaf(wre[q], sre[q], fmaf(-wim[q], sim[q], uu));
                float nim = fmaf(wre[q], sim[q], wim[q] * sre[q]);
                sre[q] = nre;
                sim[q] = nim;
            }
        }
    }
    float* bnd = g_bnd + (size_t)pair * 64 + 8 * r;
#pragma unroll
    for (int q = 0; q < 4; q++) {
        bnd[2 * q]     = sre[q];
        bnd[2 * q + 1] = sim[q];
    }
}

// ---------------- kernel 2b: combine chunk states ------------------------------
__global__ void scanB_kernel(int layer)
{
    int idx = blockIdx.x * blockDim.x + threadIdx.x;   // ch*32 + n
    if (idx >= BB * DM * N2C) return;
    int ch = idx >> 5;
    int n  = idx & 31;
    int d  = ch & (DM - 1);
    float wpre = g_wpre[(layer * DM + d) * N2C + n];
    float wpim = g_wpim[(layer * DM + d) * N2C + n];
    float Sre = 0.f, Sim = 0.f;
    size_t base = (size_t)ch * NCH * 64 + n * 2;
#pragma unroll
    for (int c = 0; c < NCH; c++) {
        g_state[base + c * 64]     = Sre;
        g_state[base + c * 64 + 1] = Sim;
        float rre = g_bnd[base + c * 64];
        float rim = g_bnd[base + c * 64 + 1];
        float nre = fmaf(wpre, Sre, fmaf(-wpim, Sim, rre));
        Sim = fmaf(wpre, Sim, fmaf(wpim, Sre, rim));
        Sre = nre;
    }
}

// ---------------- kernel 2c: output scan + GELU + fused transpose/split -------
// grid (NCH, 128): block = 32 consecutive channels x 1 chunk.
__global__ void scanC_kernel(const float* __restrict__ Dskip, int layer)
{
    __shared__ float tile[32][65];
    int tid  = threadIdx.x;
    int wid  = tid >> 5;
    int lane = tid & 31;
    int g = lane >> 3;
    int r = lane & 7;
    int chunk = blockIdx.x;
    int chgrp = blockIdx.y;
    int chl = wid * 4 + g;           // 0..31 channel within block
    int ch  = chgrp * 32 + chl;
    int d = ch & (DM - 1);
    int b = ch >> 9;
    int d0 = (chgrp & 15) * 32;

    int pbase = (layer * DM + d) * N2C + 4 * r;
    float wre[4], wim[4], cre[4], cim[4];
#pragma unroll
    for (int q = 0; q < 4; q++) {
        wre[q] = g_wre[pbase + q];
        wim[q] = g_wim[pbase + q];
        cre[q] = g_cre[pbase + q];
        cim[q] = g_cim[pbase + q];
    }
    float dsk = Dskip[layer * DM + d];

    // initial state for this chunk
    float sre[4], sim[4];
    {
        const float* st = g_state + ((size_t)ch * NCH + chunk) * 64 + 8 * r;
#pragma unroll
        for (int q = 0; q < 4; q++) {
            sre[q] = st[2 * q];
            sim[q] = st[2 * q + 1];
        }
    }

    const float* u = g_h + (size_t)ch * LL + chunk * CH;
    size_t outrow0 = ((size_t)b * LL + chunk * CH) * DM + d0;

    for (int base = 0; base < CH; base += 32) {
        float uv[4];
#pragma unroll
        for (int k = 0; k < 4; k++) uv[k] = u[base + r + 8 * k];
        float yr[4] = {0.f, 0.f, 0.f, 0.f};
#pragma unroll
        for (int j = 0; j < 32; j++) {
            float uu = __shfl_sync(0xffffffffu, uv[j >> 3], (j & 7), 8);
            float c = 0.f;
#pragma unroll
            for (int q = 0; q < 4; q++) {
                float nre = fmaf(wre[q], sre[q], fmaf(-wim[q], sim[q], uu));
                float nim = fmaf(wre[q], sim[q], wim[q] * sre[q]);
                sre[q] = nre;
                sim[q] = nim;
                c = fmaf(cre[q], nre, c);
                c = fmaf(-cim[q], nim, c);
            }
            c += __shfl_xor_sync(0xffffffffu, c, 4);
            c += __shfl_xor_sync(0xffffffffu, c, 2);
            c += __shfl_xor_sync(0xffffffffu, c, 1);
            if (r == (j & 7)) yr[j >> 3] = c;
        }
        int off = base & 32;
#pragma unroll
        for (int k = 0; k < 4; k++) {
            float v = fmaf(dsk, uv[k], yr[k]);
            float ge = 0.5f * v * (1.0f + erff(v * 0.70710678118654752f));
            tile[chl][off + r + 8 * k] = ge;
        }
        if (base & 32) {
            // flush window [base-32, base+32)
            __syncthreads();
            int w0 = base - 32;
            int ll = tid >> 2;          // 0..63
            int dd0 = (tid & 3) * 8;
            __align__(16) __nv_bfloat16 hh[8];
            __align__(16) __nv_bfloat16 lo[8];
#pragma unroll
            for (int i = 0; i < 8; i++) {
                float v = tile[dd0 + i][ll];
                __nv_bfloat16 h = __float2bfloat16(v);
                hh[i] = h;
                lo[i] = __float2bfloat16(v - __bfloat162float(h));
            }
            size_t dst = outrow0 + (size_t)(w0 + ll) * DM + dd0;
            *(uint4*)(g_yth + dst) = *(uint4*)hh;
            *(uint4*)(g_ytl + dst) = *(uint4*)lo;
            __syncthreads();
        }
    }
}

// ---------------- kernel 3: HMMA bf16-split GEMM + GLU + residual -------------
#define STAGE 65536
#define OFF_AH 0
#define OFF_AL 16384
#define OFF_BH 32768
#define OFF_BL 49152

__global__ void __launch_bounds__(256, 1)
gemm_mma_kernel(const float* __restrict__ bout, int layer)
{
    extern __shared__ char dsm[];
    uint32_t sb = smem_u32(dsm);

    const int tid  = threadIdx.x;
    const int wid  = tid >> 5;
    const int lane = tid & 31;
    const int wm   = wid >> 2;
    const int wn   = wid & 3;
    const int n0   = blockIdx.x * 128;
    const int m0   = blockIdx.y * 64;
    const int bb   = blockIdx.z;

    const __nv_bfloat16* Wh = g_wh + (size_t)layer * 2 * DM * DM;
    const __nv_bfloat16* Wl = g_wl + (size_t)layer * 2 * DM * DM;
    const __nv_bfloat16* Bh = g_yth + (size_t)bb * LL * DM;
    const __nv_bfloat16* Bl = g_ytl + (size_t)bb * LL * DM;

    auto load_stage = [&](int c) {
        int buf = c & 1;
        int kb = c * 64;
        uint32_t base = sb + buf * STAGE;
#pragma unroll
        for (int i = 0; i < 4; i++) {
            int v = tid + (i << 8);
            int row = v >> 3;
            int seg = v & 7;
            uint32_t dsw = SW128((uint32_t)(row * 128 + seg * 16));
            int p = (row < 64) ? (m0 + row) : (448 + m0 + row);
            size_t ao = (size_t)p * DM + kb + seg * 8;
            cpa16(base + OFF_AH + dsw, Wh + ao);
            cpa16(base + OFF_AL + dsw, Wl + ao);
            size_t bo = (size_t)(n0 + row) * DM + kb + seg * 8;
            cpa16(base + OFF_BH + dsw, Bh + bo);
            cpa16(base + OFF_BL + dsw, Bl + bo);
        }
        asm volatile("cp.async.commit_group;" ::: "memory");
    };

    float acc[4][4][4];
#pragma unroll
    for (int i = 0; i < 4; i++)
#pragma unroll
        for (int j = 0; j < 4; j++)
#pragma unroll
            for (int k = 0; k < 4; k++) acc[i][j][k] = 0.f;

    load_stage(0);
    load_stage(1);

    for (int s = 0; s < 8; ++s) {
        if (s < 7) asm volatile("cp.async.wait_group 1;" ::: "memory");
        else       asm volatile("cp.async.wait_group 0;" ::: "memory");
        __syncthreads();

        uint32_t base = sb + (s & 1) * STAGE;
#pragma unroll
        for (int k16 = 0; k16 < 4; ++k16) {
            uint32_t ah[4][4], al[4][4], bhf[4][2], blf[4][2];
#pragma unroll
            for (int mf = 0; mf < 4; ++mf) {
                int rowbase = (mf < 2) ? (wm * 32 + mf * 16)
                                       : (64 + wm * 32 + (mf - 2) * 16);
                int row = rowbase + (lane & 15);
                uint32_t off = SW128((uint32_t)(row * 128 + k16 * 32 + ((lane >> 4) << 4)));
                LDMX4(ah[mf], base + OFF_AH + off);
                LDMX4(al[mf], base + OFF_AL + off);
            }
#pragma unroll
            for (int pr = 0; pr < 2; ++pr) {
                int row = wn * 32 + pr * 16 + (lane & 7) + ((lane >> 4) << 3);
                uint32_t off = SW128((uint32_t)(row * 128 + k16 * 32 + (((lane >> 3) & 1) << 4)));
                uint32_t t[4];
                LDMX4(t, base + OFF_BH + off);
                bhf[2 * pr][0] = t[0]; bhf[2 * pr][1] = t[1];
                bhf[2 * pr + 1][0] = t[2]; bhf[2 * pr + 1][1] = t[3];
                LDMX4(t, base + OFF_BL + off);
                blf[2 * pr][0] = t[0]; blf[2 * pr][1] = t[1];
                blf[2 * pr + 1][0] = t[2]; blf[2 * pr + 1][1] = t[3];
            }
#pragma unroll
            for (int mf = 0; mf < 4; ++mf)
#pragma unroll
                for (int nf = 0; nf < 4; ++nf) {
                    MMA16816(acc[mf][nf], ah[mf], bhf[nf]);
                    MMA16816(acc[mf][nf], al[mf], bhf[nf]);
                    MMA16816(acc[mf][nf], ah[mf], blf[nf]);
                }
        }
        __syncthreads();
        if (s < 6) load_stage(s + 2);
    }

    const float* bo = bout + layer * 2 * DM;
    int groupid = lane >> 2;
    int tg = lane & 3;
#pragma unroll
    for (int mf = 0; mf < 2; ++mf) {
#pragma unroll
        for (int rp = 0; rp < 2; ++rp) {
            int o = m0 + wm * 32 + mf * 16 + groupid + rp * 8;
            float b1 = bo[o];
            float b2 = bo[DM + o];
            float* H = g_h + ((size_t)bb * DM + o) * LL + n0 + wn * 32;
#pragma unroll
            for (int nf = 0; nf < 4; ++nf) {
                float a0 = acc[mf][nf][rp * 2 + 0] + b1;
                float a1 = acc[mf][nf][rp * 2 + 1] + b1;
                float g0 = acc[mf + 2][nf][rp * 2 + 0] + b2;
                float g1 = acc[mf + 2][nf][rp * 2 + 1] + b2;
                float z0 = a0 / (1.0f + expf(-g0));
                float z1 = a1 / (1.0f + expf(-g1));
                float2* ptr = (float2*)(H + nf * 8 + tg * 2);
                float2 h2 = *ptr;
                h2.x += z0;
                h2.y += z1;
                *ptr = h2;
            }
        }
    }
}

// ---------------- kernel 4: LayerNorm over channel dim (in place) -------------
__global__ void ln_kernel(const float* __restrict__ ln_g,
                          const float* __restrict__ ln_b, int layer)
{
    int l = blockIdx.x * blockDim.x + threadIdx.x;
    int b = blockIdx.y;
    const float* gv = ln_g + layer * DM;
    const float* bv = ln_b + layer * DM;
    float* H = g_h + (size_t)b * DM * LL + l;
    float s = 0.f, s2 = 0.f;
#pragma unroll 8
    for (int d = 0; d < DM; d++) {
        float v = H[(size_t)d * LL];
        s += v;
        s2 = fmaf(v, v, s2);
    }
    float mu  = s * (1.0f / DM);
    float var = s2 * (1.0f / DM) - mu * mu;
    float inv = rsqrtf(var + 1e-5f);
#pragma unroll 8
    for (int d = 0; d < DM; d++) {
        float v = H[(size_t)d * LL];
        H[(size_t)d * LL] = (v - mu) * inv * gv[d] + bv[d];
    }
}

// ---------------- kernel 5: mean over L ---------------------------------------
__global__ void mean_kernel()
{
    int ch = blockIdx.x;
    const float* H = g_h + (size_t)ch * LL;
    float s = 0.f;
    for (int l = threadIdx.x; l < LL; l += 128) s += H[l];
    __shared__ float sm[128];
    sm[threadIdx.x] = s;
    __syncthreads();
    for (int o = 64; o > 0; o >>= 1) {
        if (threadIdx.x < o) sm[threadIdx.x] += sm[threadIdx.x + o];
        __syncthreads();
    }
    if (threadIdx.x == 0) g_hbar[ch] = sm[0] * (1.0f / LL);
}

// ---------------- kernel 6: stats head + output layout ------------------------
__global__ void stats_kernel(const float* __restrict__ Wstats,
                             const float* __restrict__ bstats,
                             float* __restrict__ out)
{
    int idx = blockIdx.x * blockDim.x + threadIdx.x;
    if (idx >= BB * 2 * LAT) return;
    int b = idx / (2 * LAT);
    int o = idx % (2 * LAT);
    const float* hb = g_hbar + b * DM;
    const float* w  = Wstats + (size_t)o * DM;
    float s = bstats[o];
#pragma unroll 8
    for (int d = 0; d < DM; d++) s = fmaf(hb[d], w[d], s);
    int pos = (o < LAT) ? (b * LAT + o) : (BB * LAT + b * LAT + (o - LAT));
    out[pos] = s;
}

// ---------------- launch ------------------------------------------------------
extern "C" void kernel_launch(void* const* d_in, const int* in_sizes, int n_in,
                              void* d_out, int out_size)
{
    const float* x          = (const float*)d_in[0];
    const float* Wproj      = (const float*)d_in[1];
    const float* bproj      = (const float*)d_in[2];
    const float* pos        = (const float*)d_in[3];
    const float* log_dt     = (const float*)d_in[4];
    const float* log_A_real = (const float*)d_in[5];
    const float* A_imag     = (const float*)d_in[6];
    const float* C_re       = (const float*)d_in[7];
    const float* C_im       = (const float*)d_in[8];
    const float* Dskip      = (const float*)d_in[9];
    const float* Wout       = (const float*)d_in[10];
    const float* bout       = (const float*)d_in[11];
    const float* ln_g       = (const float*)d_in[12];
    const float* ln_b       = (const float*)d_in[13];
    const float* Wstats     = (const float*)d_in[14];
    const float* bstats     = (const float*)d_in[15];
    float* out = (float*)d_out;

    const int gemm_smem = 2 * STAGE;
    cudaFuncSetAttribute(gemm_mma_kernel,
                         cudaFuncAttributeMaxDynamicSharedMemorySize, gemm_smem);

    precompute_kernel<<<(NLAY * DM * N2C) / 256, 256>>>(log_dt, log_A_real, A_imag, C_re, C_im);
    wsplit_kernel<<<(NLAY * 2 * DM * DM) / 256, 256>>>(Wout);
    proj_kernel<<<(BB * DM * LL) / 256, 256>>>(x, Wproj, bproj, pos);

    for (int layer = 0; layer < NLAY; ++layer) {
        scanA_kernel<<<(BB * DM * NCH * 8) / 256, 256>>>(layer);
        scanB_kernel<<<(BB * DM * N2C) / 256, 256>>>(layer);
        scanC_kernel<<<dim3(NCH, (BB * DM) / 32), 256>>>(Dskip, layer);
        dim3 ggrid(LL / 128, DM / 64, BB);
        gemm_mma_kernel<<<ggrid, 256, gemm_smem>>>(bout, layer);
        dim3 lgrid(LL / 256, BB);
        ln_kernel<<<lgrid, 256>>>(ln_g, ln_b, layer);
    }

    mean_kernel<<<BB * DM, 128>>>();
    stats_kernel<<<(BB * 2 * LAT + 255) / 256, 256>>>(Wstats, bstats, out);
}

// round 11
// speedup vs baseline: 1.7488x; 1.0956x over previous
#include <cuda_runtime.h>
#include <cuda_bf16.h>
#include <math.h>
#include <stdint.h>

#define BB 8
#define CINN 3
#define DM 512
#define N2C 32
#define NLAY 4
#define LL 4096
#define LAT 256
#define NCH 16      // chunks per sequence
#define CH 256      // chunk length

// ---------------- scratch (device globals; no allocation allowed) -------------
__device__ float g_h[BB * DM * LL];              // activations [b][d][l]
__device__ __nv_bfloat16 g_yth[BB * LL * DM];    // Y^T hi  [b][l][d]
__device__ __nv_bfloat16 g_ytl[BB * LL * DM];    // Y^T lo  [b][l][d]
__device__ __nv_bfloat16 g_wh[NLAY * 2 * DM * DM];
__device__ __nv_bfloat16 g_wl[NLAY * 2 * DM * DM];
__device__ float g_wre[NLAY * DM * N2C];
__device__ float g_wim[NLAY * DM * N2C];
__device__ float g_cre[NLAY * DM * N2C];
__device__ float g_cim[NLAY * DM * N2C];
__device__ float g_wpre[NLAY * DM * N2C];        // w^CH real
__device__ float g_wpim[NLAY * DM * N2C];        // w^CH imag
__device__ float g_bnd[BB * DM * NCH * N2C * 2]; // chunk remainders r_c
__device__ float g_hbar[BB * DM];

// ---------------- helpers -----------------------------------------------------
__device__ __forceinline__ uint32_t smem_u32(const void* p) {
    uint32_t a;
    asm("{ .reg .u64 t; cvta.to.shared.u64 t, %1; cvt.u32.u64 %0, t; }" : "=r"(a) : "l"(p));
    return a;
}
#define SW128(o) ((o) ^ (((o) >> 3) & 0x70))

#define LDMX4(r, addr) \
    asm volatile("ldmatrix.sync.aligned.m8n8.x4.shared.b16 {%0,%1,%2,%3}, [%4];" \
        : "=r"((r)[0]), "=r"((r)[1]), "=r"((r)[2]), "=r"((r)[3]) : "r"(addr))

#define MMA16816(c, a, b) \
    asm volatile("mma.sync.aligned.m16n8k16.row.col.f32.bf16.bf16.f32 " \
        "{%0,%1,%2,%3}, {%4,%5,%6,%7}, {%8,%9}, {%0,%1,%2,%3};" \
        : "+f"((c)[0]), "+f"((c)[1]), "+f"((c)[2]), "+f"((c)[3]) \
        : "r"((a)[0]), "r"((a)[1]), "r"((a)[2]), "r"((a)[3]), \
          "r"((b)[0]), "r"((b)[1]))

__device__ __forceinline__ void cpa16(uint32_t dst, const void* src) {
    asm volatile("cp.async.cg.shared.global [%0], [%1], 16;" :: "r"(dst), "l"(src));
}

// ---- packed fp32x2 (Blackwell FFMA2 path) ----
#define PK2(d, a, b) \
    asm("mov.b64 %0, {%1, %2};" : "=l"(d) : "r"(__float_as_uint(a)), "r"(__float_as_uint(b)))
#define UPK2(a, b, d) \
    { uint32_t _x, _y; asm("mov.b64 {%0, %1}, %2;" : "=r"(_x), "=r"(_y) : "l"(d)); \
      (a) = __uint_as_float(_x); (b) = __uint_as_float(_y); }
#define FMA2(d, a, b, c) \
    asm("fma.rn.f32x2 %0, %1, %2, %3;" : "=l"(d) : "l"(a), "l"(b), "l"(c))
#define MUL2(d, a, b) \
    asm("mul.rn.f32x2 %0, %1, %2;" : "=l"(d) : "l"(a), "l"(b))

// ---------------- kernel 0: per-layer SSM parameter precompute ----------------
__global__ void precompute_kernel(const float* __restrict__ log_dt,
                                  const float* __restrict__ log_A_real,
                                  const float* __restrict__ A_imag,
                                  const float* __restrict__ C_re,
                                  const float* __restrict__ C_im)
{
    int idx = blockIdx.x * blockDim.x + threadIdx.x;
    if (idx >= NLAY * DM * N2C) return;
    int hd = idx / N2C;
    float dt  = expf(log_dt[hd]);
    float are = -expf(log_A_real[idx]);
    float aim = A_imag[idx];
    float dre = are * dt;
    float dim = aim * dt;
    float er  = expf(dre);
    float wre = er * cosf(dim);
    float wim = er * sinf(dim);
    float Ere = wre - 1.0f;
    float Eim = wim;
    float inv = 1.0f / (are * are + aim * aim);
    float fre = (Ere * are + Eim * aim) * inv;
    float fim = (Eim * are - Ere * aim) * inv;
    float crr = C_re[idx], cii = C_im[idx];
    g_wre[idx] = wre;
    g_wim[idx] = wim;
    g_cre[idx] = 2.0f * (crr * fre - cii * fim);
    g_cim[idx] = 2.0f * (crr * fim + cii * fre);
    float pr = expf((float)CH * dre);
    g_wpre[idx] = pr * cosf((float)CH * dim);
    g_wpim[idx] = pr * sinf((float)CH * dim);
}

// ---------------- kernel 0b: bf16-split Wout ----------------------------------
__global__ void wsplit_kernel(const float* __restrict__ Wout)
{
    int idx = blockIdx.x * blockDim.x + threadIdx.x;
    if (idx >= NLAY * 2 * DM * DM) return;
    float v = Wout[idx];
    __nv_bfloat16 h = __float2bfloat16(v);
    g_wh[idx] = h;
    g_wl[idx] = __float2bfloat16(v - __bfloat162float(h));
}

// ---------------- kernel 1: input projection + positional embedding ----------
__global__ void proj_kernel(const float* __restrict__ x,
                            const float* __restrict__ Wproj,
                            const float* __restrict__ bproj,
                            const float* __restrict__ pos)
{
    int idx = blockIdx.x * blockDim.x + threadIdx.x;
    if (idx >= BB * DM * LL) return;
    int l = idx & (LL - 1);
    int d = (idx >> 12) & (DM - 1);
    int b = idx >> 21;
    const float* xb = x + (size_t)b * CINN * LL;
    float v = bproj[d];
    v = fmaf(Wproj[d * 3 + 0], xb[l], v);
    v = fmaf(Wproj[d * 3 + 1], xb[LL + l], v);
    v = fmaf(Wproj[d * 3 + 2], xb[2 * LL + l], v);
    v += pos[(size_t)l * DM + d];
    g_h[idx] = v;
}

// ---------------- kernel 2a: chunk remainders (state-only, packed f32x2) ------
// 8 lanes per (channel, chunk); 4 states per lane packed as 2 f32x2 pairs.
// Only chunks 0..14 (remainder of chunk 15 is never consumed).
__global__ void scanA_kernel(int layer)
{
    int gtid = blockIdx.x * blockDim.x + threadIdx.x;
    int pair = gtid >> 3;
    int r    = gtid & 7;
    int ch    = pair / (NCH - 1);
    int chunk = pair % (NCH - 1);
    int d = ch & (DM - 1);

    int pbase = (layer * DM + d) * N2C + 4 * r;
    uint64_t wre2[2], wim2[2], nwim2[2];
#pragma unroll
    for (int p = 0; p < 2; p++) {
        float w0 = g_wre[pbase + 2 * p], w1 = g_wre[pbase + 2 * p + 1];
        float i0 = g_wim[pbase + 2 * p], i1 = g_wim[pbase + 2 * p + 1];
        PK2(wre2[p], w0, w1);
        PK2(wim2[p], i0, i1);
        PK2(nwim2[p], -i0, -i1);
    }

    const float* u = g_h + (size_t)ch * LL + chunk * CH;
    uint64_t sre2[2] = {0ull, 0ull}, sim2[2] = {0ull, 0ull};

    for (int base = 0; base < CH; base += 32) {
        float uv[4];
#pragma unroll
        for (int k = 0; k < 4; k++) uv[k] = u[base + r + 8 * k];
#pragma unroll
        for (int j = 0; j < 32; j++) {
            float uu = __shfl_sync(0xffffffffu, uv[j >> 3], (j & 7), 8);
            uint64_t uup;
            PK2(uup, uu, uu);
#pragma unroll
            for (int p = 0; p < 2; p++) {
                uint64_t t, rr, nre, nim;
                MUL2(t, wim2[p], sre2[p]);
                FMA2(rr, nwim2[p], sim2[p], uup);
                FMA2(nre, wre2[p], sre2[p], rr);
                FMA2(nim, wre2[p], sim2[p], t);
                sre2[p] = nre;
                sim2[p] = nim;
            }
        }
    }
    float* bnd = g_bnd + ((size_t)ch * NCH + chunk) * 64 + 8 * r;
#pragma unroll
    for (int p = 0; p < 2; p++) {
        float r0, r1, i0, i1;
        UPK2(r0, r1, sre2[p]);
        UPK2(i0, i1, sim2[p]);
        bnd[4 * p + 0] = r0;
        bnd[4 * p + 1] = i0;
        bnd[4 * p + 2] = r1;
        bnd[4 * p + 3] = i1;
    }
}

// ---------------- kernel 2c: output scan (packed) + GELU + fused transp/split -
// grid (NCH, 128): block = 32 consecutive channels x 1 chunk.
// Prologue folds chunk-prefix states from g_bnd (replaces old scanB kernel).
__global__ void scanC_kernel(const float* __restrict__ Dskip, int layer)
{
    __shared__ float tile[32][65];
    __shared__ float sSre[32][32];
    __shared__ float sSim[32][32];
    int tid  = threadIdx.x;
    int wid  = tid >> 5;
    int lane = tid & 31;
    int g = lane >> 3;
    int r = lane & 7;
    int chunk = blockIdx.x;
    int chgrp = blockIdx.y;
    int chl = wid * 4 + g;
    int chn = chgrp * 32 + chl;
    int d = chn & (DM - 1);
    int b = chn >> 9;
    int d0 = (chgrp & 15) * 32;

    // ---- prologue: compute incoming state S_chunk for all 32 channels x 32 n
    {
#pragma unroll
        for (int it = 0; it < 4; it++) {
            int pid = tid + 256 * it;        // chl*32 + n
            int pc = pid >> 5;
            int n  = pid & 31;
            int pch = chgrp * 32 + pc;
            int pd  = pch & (DM - 1);
            float wpre = g_wpre[(layer * DM + pd) * N2C + n];
            float wpim = g_wpim[(layer * DM + pd) * N2C + n];
            float Sre = 0.f, Sim = 0.f;
            const float* bnd = g_bnd + (size_t)pch * NCH * 64 + 2 * n;
            for (int k = 0; k < chunk; k++) {
                float rre = bnd[k * 64];
                float rim = bnd[k * 64 + 1];
                float nre = fmaf(wpre, Sre, fmaf(-wpim, Sim, rre));
                Sim = fmaf(wpre, Sim, fmaf(wpim, Sre, rim));
                Sre = nre;
            }
            sSre[pc][n] = Sre;
            sSim[pc][n] = Sim;
        }
        __syncthreads();
    }

    int pbase = (layer * DM + d) * N2C + 4 * r;
    uint64_t wre2[2], wim2[2], nwim2[2], cre2[2], ncim2[2];
#pragma unroll
    for (int p = 0; p < 2; p++) {
        float w0 = g_wre[pbase + 2 * p], w1 = g_wre[pbase + 2 * p + 1];
        float i0 = g_wim[pbase + 2 * p], i1 = g_wim[pbase + 2 * p + 1];
        float c0 = g_cre[pbase + 2 * p], c1 = g_cre[pbase + 2 * p + 1];
        float m0 = g_cim[pbase + 2 * p], m1 = g_cim[pbase + 2 * p + 1];
        PK2(wre2[p], w0, w1);
        PK2(wim2[p], i0, i1);
        PK2(nwim2[p], -i0, -i1);
        PK2(cre2[p], c0, c1);
        PK2(ncim2[p], -m0, -m1);
    }
    float dsk = Dskip[layer * DM + d];

    uint64_t sre2[2], sim2[2];
#pragma unroll
    for (int p = 0; p < 2; p++) {
        PK2(sre2[p], sSre[chl][4 * r + 2 * p], sSre[chl][4 * r + 2 * p + 1]);
        PK2(sim2[p], sSim[chl][4 * r + 2 * p], sSim[chl][4 * r + 2 * p + 1]);
    }
    __syncthreads();

    const float* u = g_h + (size_t)chn * LL + chunk * CH;
    size_t outrow0 = ((size_t)b * LL + chunk * CH) * DM + d0;

    for (int base = 0; base < CH; base += 32) {
        float uv[4];
#pragma unroll
        for (int k = 0; k < 4; k++) uv[k] = u[base + r + 8 * k];
        float yr[4] = {0.f, 0.f, 0.f, 0.f};
#pragma unroll
        for (int j = 0; j < 32; j++) {
            float uu = __shfl_sync(0xffffffffu, uv[j >> 3], (j & 7), 8);
            uint64_t uup;
            PK2(uup, uu, uu);
            uint64_t c2 = 0ull;
#pragma unroll
            for (int p = 0; p < 2; p++) {
                uint64_t t, rr, nre, nim;
                MUL2(t, wim2[p], sre2[p]);
                FMA2(rr, nwim2[p], sim2[p], uup);
                FMA2(nre, wre2[p], sre2[p], rr);
                FMA2(nim, wre2[p], sim2[p], t);
                sre2[p] = nre;
                sim2[p] = nim;
                FMA2(c2, cre2[p], nre, c2);
                FMA2(c2, ncim2[p], nim, c2);
            }
            float clo, chi;
            UPK2(clo, chi, c2);
            float c = clo + chi;
            c += __shfl_xor_sync(0xffffffffu, c, 4);
            c += __shfl_xor_sync(0xffffffffu, c, 2);
            c += __shfl_xor_sync(0xffffffffu, c, 1);
            if (r == (j & 7)) yr[j >> 3] = c;
        }
        int off = base & 32;
#pragma unroll
        for (int k = 0; k < 4; k++) {
            float v = fmaf(dsk, uv[k], yr[k]);
            float ge = 0.5f * v * (1.0f + erff(v * 0.70710678118654752f));
            tile[chl][off + r + 8 * k] = ge;
        }
        if (base & 32) {
            __syncthreads();
            int w0 = base - 32;
            int ll = tid >> 2;
            int dd0 = (tid & 3) * 8;
            __align__(16) __nv_bfloat16 hh[8];
            __align__(16) __nv_bfloat16 lo[8];
#pragma unroll
            for (int i = 0; i < 8; i++) {
                float v = tile[dd0 + i][ll];
                __nv_bfloat16 h = __float2bfloat16(v);
                hh[i] = h;
                lo[i] = __float2bfloat16(v - __bfloat162float(h));
            }
            size_t dst = outrow0 + (size_t)(w0 + ll) * DM + dd0;
            *(uint4*)(g_yth + dst) = *(uint4*)hh;
            *(uint4*)(g_ytl + dst) = *(uint4*)lo;
            __syncthreads();
        }
    }
}

// ---------------- kernel 3: HMMA bf16-split GEMM + GLU + residual -------------
#define STAGE 65536
#define OFF_AH 0
#define OFF_AL 16384
#define OFF_BH 32768
#define OFF_BL 49152

__global__ void __launch_bounds__(256, 1)
gemm_mma_kernel(const float* __restrict__ bout, int layer)
{
    extern __shared__ char dsm[];
    uint32_t sb = smem_u32(dsm);

    const int tid  = threadIdx.x;
    const int wid  = tid >> 5;
    const int lane = tid & 31;
    const int wm   = wid >> 2;
    const int wn   = wid & 3;
    const int n0   = blockIdx.x * 128;
    const int m0   = blockIdx.y * 64;
    const int bb   = blockIdx.z;

    const __nv_bfloat16* Wh = g_wh + (size_t)layer * 2 * DM * DM;
    const __nv_bfloat16* Wl = g_wl + (size_t)layer * 2 * DM * DM;
    const __nv_bfloat16* Bh = g_yth + (size_t)bb * LL * DM;
    const __nv_bfloat16* Bl = g_ytl + (size_t)bb * LL * DM;

    auto load_stage = [&](int c) {
        int buf = c & 1;
        int kb = c * 64;
        uint32_t base = sb + buf * STAGE;
#pragma unroll
        for (int i = 0; i < 4; i++) {
            int v = tid + (i << 8);
            int row = v >> 3;
            int seg = v & 7;
            uint32_t dsw = SW128((uint32_t)(row * 128 + seg * 16));
            int p = (row < 64) ? (m0 + row) : (448 + m0 + row);
            size_t ao = (size_t)p * DM + kb + seg * 8;
            cpa16(base + OFF_AH + dsw, Wh + ao);
            cpa16(base + OFF_AL + dsw, Wl + ao);
            size_t bo = (size_t)(n0 + row) * DM + kb + seg * 8;
            cpa16(base + OFF_BH + dsw, Bh + bo);
            cpa16(base + OFF_BL + dsw, Bl + bo);
        }
        asm volatile("cp.async.commit_group;" ::: "memory");
    };

    float acc[4][4][4];
#pragma unroll
    for (int i = 0; i < 4; i++)
#pragma unroll
        for (int j = 0; j < 4; j++)
#pragma unroll
            for (int k = 0; k < 4; k++) acc[i][j][k] = 0.f;

    load_stage(0);
    load_stage(1);

    for (int s = 0; s < 8; ++s) {
        if (s < 7) asm volatile("cp.async.wait_group 1;" ::: "memory");
        else       asm volatile("cp.async.wait_group 0;" ::: "memory");
        __syncthreads();

        uint32_t base = sb + (s & 1) * STAGE;
#pragma unroll
        for (int k16 = 0; k16 < 4; ++k16) {
            uint32_t ah[4][4], al[4][4], bhf[4][2], blf[4][2];
#pragma unroll
            for (int mf = 0; mf < 4; ++mf) {
                int rowbase = (mf < 2) ? (wm * 32 + mf * 16)
                                       : (64 + wm * 32 + (mf - 2) * 16);
                int row = rowbase + (lane & 15);
                uint32_t off = SW128((uint32_t)(row * 128 + k16 * 32 + ((lane >> 4) << 4)));
                LDMX4(ah[mf], base + OFF_AH + off);
                LDMX4(al[mf], base + OFF_AL + off);
            }
#pragma unroll
            for (int pr = 0; pr < 2; ++pr) {
                int row = wn * 32 + pr * 16 + (lane & 7) + ((lane >> 4) << 3);
                uint32_t off = SW128((uint32_t)(row * 128 + k16 * 32 + (((lane >> 3) & 1) << 4)));
                uint32_t t[4];
                LDMX4(t, base + OFF_BH + off);
                bhf[2 * pr][0] = t[0]; bhf[2 * pr][1] = t[1];
                bhf[2 * pr + 1][0] = t[2]; bhf[2 * pr + 1][1] = t[3];
                LDMX4(t, base + OFF_BL + off);
                blf[2 * pr][0] = t[0]; blf[2 * pr][1] = t[1];
                blf[2 * pr + 1][0] = t[2]; blf[2 * pr + 1][1] = t[3];
            }
#pragma unroll
            for (int mf = 0; mf < 4; ++mf)
#pragma unroll
                for (int nf = 0; nf < 4; ++nf) {
                    MMA16816(acc[mf][nf], ah[mf], bhf[nf]);
                    MMA16816(acc[mf][nf], al[mf], bhf[nf]);
                    MMA16816(acc[mf][nf], ah[mf], blf[nf]);
                }
        }
        __syncthreads();
        if (s < 6) load_stage(s + 2);
    }

    const float* bo = bout + layer * 2 * DM;
    int groupid = lane >> 2;
    int tg = lane & 3;
#pragma unroll
    for (int mf = 0; mf < 2; ++mf) {
#pragma unroll
        for (int rp = 0; rp < 2; ++rp) {
            int o = m0 + wm * 32 + mf * 16 + groupid + rp * 8;
            float b1 = bo[o];
            float b2 = bo[DM + o];
            float* H = g_h + ((size_t)bb * DM + o) * LL + n0 + wn * 32;
#pragma unroll
            for (int nf = 0; nf < 4; ++nf) {
                float a0 = acc[mf][nf][rp * 2 + 0] + b1;
                float a1 = acc[mf][nf][rp * 2 + 1] + b1;
                float g0 = acc[mf + 2][nf][rp * 2 + 0] + b2;
                float g1 = acc[mf + 2][nf][rp * 2 + 1] + b2;
                float z0 = a0 / (1.0f + expf(-g0));
                float z1 = a1 / (1.0f + expf(-g1));
                float2* ptr = (float2*)(H + nf * 8 + tg * 2);
                float2 h2 = *ptr;
                h2.x += z0;
                h2.y += z1;
                *ptr = h2;
            }
        }
    }
}

// ---------------- kernel 4: LayerNorm over channel dim (4-way split) ----------
// block = 256 threads = 64 l-positions x 4 d-groups of 128; grid (LL/64, BB)
__global__ void ln_kernel(const float* __restrict__ ln_g,
                          const float* __restrict__ ln_b, int layer)
{
    __shared__ float sS[4][64];
    __shared__ float sS2[4][64];
    __shared__ float sMu[64];
    __shared__ float sRs[64];
    int b  = blockIdx.y;
    int l0 = blockIdx.x * 64;
    int tid = threadIdx.x;
    int ll  = tid & 63;
    int grp = tid >> 6;
    float* H = g_h + (size_t)b * DM * LL + (size_t)grp * 128 * LL + l0 + ll;
    float s = 0.f, s2 = 0.f;
#pragma unroll 8
    for (int d = 0; d < 128; d++) {
        float v = H[(size_t)d * LL];
        s += v;
        s2 = fmaf(v, v, s2);
    }
    sS[grp][ll] = s;
    sS2[grp][ll] = s2;
    __syncthreads();
    if (tid < 64) {
        float st  = sS[0][tid] + sS[1][tid] + sS[2][tid] + sS[3][tid];
        float st2 = sS2[0][tid] + sS2[1][tid] + sS2[2][tid] + sS2[3][tid];
        float mu  = st * (1.0f / DM);
        float var = st2 * (1.0f / DM) - mu * mu;
        sMu[tid] = mu;
        sRs[tid] = rsqrtf(var + 1e-5f);
    }
    __syncthreads();
    float mu = sMu[ll];
    float rs = sRs[ll];
    const float* gv = ln_g + layer * DM + grp * 128;
    const float* bv = ln_b + layer * DM + grp * 128;
#pragma unroll 8
    for (int d = 0; d < 128; d++) {
        float v = H[(size_t)d * LL];
        H[(size_t)d * LL] = (v - mu) * rs * gv[d] + bv[d];
    }
}

// ---------------- kernel 5: mean over L ---------------------------------------
__global__ void mean_kernel()
{
    int ch = blockIdx.x;
    const float* H = g_h + (size_t)ch * LL;
    float s = 0.f;
    for (int l = threadIdx.x; l < LL; l += 128) s += H[l];
    __shared__ float sm[128];
    sm[threadIdx.x] = s;
    __syncthreads();
    for (int o = 64; o > 0; o >>= 1) {
        if (threadIdx.x < o) sm[threadIdx.x] += sm[threadIdx.x + o];
        __syncthreads();
    }
    if (threadIdx.x == 0) g_hbar[ch] = sm[0] * (1.0f / LL);
}

// ---------------- kernel 6: stats head + output layout ------------------------
__global__ void stats_kernel(const float* __restrict__ Wstats,
                             const float* __restrict__ bstats,
                             float* __restrict__ out)
{
    int idx = blockIdx.x * blockDim.x + threadIdx.x;
    if (idx >= BB * 2 * LAT) return;
    int b = idx / (2 * LAT);
    int o = idx % (2 * LAT);
    const float* hb = g_hbar + b * DM;
    const float* w  = Wstats + (size_t)o * DM;
    float s = bstats[o];
#pragma unroll 8
    for (int d = 0; d < DM; d++) s = fmaf(hb[d], w[d], s);
    int pos = (o < LAT) ? (b * LAT + o) : (BB * LAT + b * LAT + (o - LAT));
    out[pos] = s;
}

// ---------------- launch ------------------------------------------------------
extern "C" void kernel_launch(void* const* d_in, const int* in_sizes, int n_in,
                              void* d_out, int out_size)
{
    const float* x          = (const float*)d_in[0];
    const float* Wproj      = (const float*)d_in[1];
    const float* bproj      = (const float*)d_in[2];
    const float* pos        = (const float*)d_in[3];
    const float* log_dt     = (const float*)d_in[4];
    const float* log_A_real = (const float*)d_in[5];
    const float* A_imag     = (const float*)d_in[6];
    const float* C_re       = (const float*)d_in[7];
    const float* C_im       = (const float*)d_in[8];
    const float* Dskip      = (const float*)d_in[9];
    const float* Wout       = (const float*)d_in[10];
    const float* bout       = (const float*)d_in[11];
    const float* ln_g       = (const float*)d_in[12];
    const float* ln_b       = (const float*)d_in[13];
    const float* Wstats     = (const float*)d_in[14];
    const float* bstats     = (const float*)d_in[15];
    float* out = (float*)d_out;

    const int gemm_smem = 2 * STAGE;
    cudaFuncSetAttribute(gemm_mma_kernel,
                         cudaFuncAttributeMaxDynamicSharedMemorySize, gemm_smem);

    precompute_kernel<<<(NLAY * DM * N2C) / 256, 256>>>(log_dt, log_A_real, A_imag, C_re, C_im);
    wsplit_kernel<<<(NLAY * 2 * DM * DM) / 256, 256>>>(Wout);
    proj_kernel<<<(BB * DM * LL) / 256, 256>>>(x, Wproj, bproj, pos);

    for (int layer = 0; layer < NLAY; ++layer) {
        scanA_kernel<<<(BB * DM * (NCH - 1) * 8) / 256, 256>>>(layer);
        scanC_kernel<<<dim3(NCH, (BB * DM) / 32), 256>>>(Dskip, layer);
        dim3 ggrid(LL / 128, DM / 64, BB);
        gemm_mma_kernel<<<ggrid, 256, gemm_smem>>>(bout, layer);
        dim3 lgrid(LL / 64, BB);
        ln_kernel<<<lgrid, 256>>>(ln_g, ln_b, layer);
    }

    mean_kernel<<<BB * DM, 128>>>();
    stats_kernel<<<(BB * 2 * LAT + 255) / 256, 256>>>(Wstats, bstats, out);
}

// round 12
// speedup vs baseline: 1.9747x; 1.1292x over previous
#include <cuda_runtime.h>
#include <cuda_bf16.h>
#include <math.h>
#include <stdint.h>

#define BB 8
#define CINN 3
#define DM 512
#define N2C 32
#define NLAY 4
#define LL 4096
#define LAT 256
#define NCH 16      // chunks per sequence
#define CH 256      // chunk length

// ---------------- scratch (device globals; no allocation allowed) -------------
__device__ float g_h[BB * DM * LL];              // activations [b][d][l]
__device__ __nv_bfloat16 g_yth[BB * LL * DM];    // Y^T hi  [b][l][d]
__device__ __nv_bfloat16 g_wh[NLAY * 2 * DM * DM];
__device__ __nv_bfloat16 g_wl[NLAY * 2 * DM * DM];
__device__ float g_wre[NLAY * DM * N2C];
__device__ float g_wim[NLAY * DM * N2C];
__device__ float g_cre[NLAY * DM * N2C];
__device__ float g_cim[NLAY * DM * N2C];
__device__ float g_wpre[NLAY * DM * N2C];        // w^CH real
__device__ float g_wpim[NLAY * DM * N2C];        // w^CH imag
__device__ float g_bnd[BB * DM * NCH * N2C * 2]; // chunk remainders r_c
__device__ float g_hbar[BB * DM];

// ---------------- helpers -----------------------------------------------------
__device__ __forceinline__ uint32_t smem_u32(const void* p) {
    uint32_t a;
    asm("{ .reg .u64 t; cvta.to.shared.u64 t, %1; cvt.u32.u64 %0, t; }" : "=r"(a) : "l"(p));
    return a;
}
#define SW128(o) ((o) ^ (((o) >> 3) & 0x70))

#define LDMX4(r, addr) \
    asm volatile("ldmatrix.sync.aligned.m8n8.x4.shared.b16 {%0,%1,%2,%3}, [%4];" \
        : "=r"((r)[0]), "=r"((r)[1]), "=r"((r)[2]), "=r"((r)[3]) : "r"(addr))

#define MMA16816(c, a, b) \
    asm volatile("mma.sync.aligned.m16n8k16.row.col.f32.bf16.bf16.f32 " \
        "{%0,%1,%2,%3}, {%4,%5,%6,%7}, {%8,%9}, {%0,%1,%2,%3};" \
        : "+f"((c)[0]), "+f"((c)[1]), "+f"((c)[2]), "+f"((c)[3]) \
        : "r"((a)[0]), "r"((a)[1]), "r"((a)[2]), "r"((a)[3]), \
          "r"((b)[0]), "r"((b)[1]))

__device__ __forceinline__ void cpa16(uint32_t dst, const void* src) {
    asm volatile("cp.async.cg.shared.global [%0], [%1], 16;" :: "r"(dst), "l"(src));
}

// ---- packed fp32x2 (Blackwell FFMA2 path) ----
#define PK2(d, a, b) \
    asm("mov.b64 %0, {%1, %2};" : "=l"(d) : "r"(__float_as_uint(a)), "r"(__float_as_uint(b)))
#define UPK2(a, b, d) \
    { uint32_t _x, _y; asm("mov.b64 {%0, %1}, %2;" : "=r"(_x), "=r"(_y) : "l"(d)); \
      (a) = __uint_as_float(_x); (b) = __uint_as_float(_y); }
#define FMA2(d, a, b, c) \
    asm("fma.rn.f32x2 %0, %1, %2, %3;" : "=l"(d) : "l"(a), "l"(b), "l"(c))
#define MUL2(d, a, b) \
    asm("mul.rn.f32x2 %0, %1, %2;" : "=l"(d) : "l"(a), "l"(b))

// ---------------- kernel 0: per-layer SSM parameter precompute ----------------
__global__ void precompute_kernel(const float* __restrict__ log_dt,
                                  const float* __restrict__ log_A_real,
                                  const float* __restrict__ A_imag,
                                  const float* __restrict__ C_re,
                                  const float* __restrict__ C_im)
{
    int idx = blockIdx.x * blockDim.x + threadIdx.x;
    if (idx >= NLAY * DM * N2C) return;
    int hd = idx / N2C;
    float dt  = expf(log_dt[hd]);
    float are = -expf(log_A_real[idx]);
    float aim = A_imag[idx];
    float dre = are * dt;
    float dim = aim * dt;
    float er  = expf(dre);
    float wre = er * cosf(dim);
    float wim = er * sinf(dim);
    float Ere = wre - 1.0f;
    float Eim = wim;
    float inv = 1.0f / (are * are + aim * aim);
    float fre = (Ere * are + Eim * aim) * inv;
    float fim = (Eim * are - Ere * aim) * inv;
    float crr = C_re[idx], cii = C_im[idx];
    g_wre[idx] = wre;
    g_wim[idx] = wim;
    g_cre[idx] = 2.0f * (crr * fre - cii * fim);
    g_cim[idx] = 2.0f * (crr * fim + cii * fre);
    float pr = expf((float)CH * dre);
    g_wpre[idx] = pr * cosf((float)CH * dim);
    g_wpim[idx] = pr * sinf((float)CH * dim);
}

// ---------------- kernel 0b: bf16-split Wout ----------------------------------
__global__ void wsplit_kernel(const float* __restrict__ Wout)
{
    int idx = blockIdx.x * blockDim.x + threadIdx.x;
    if (idx >= NLAY * 2 * DM * DM) return;
    float v = Wout[idx];
    __nv_bfloat16 h = __float2bfloat16(v);
    g_wh[idx] = h;
    g_wl[idx] = __float2bfloat16(v - __bfloat162float(h));
}

// ---------------- kernel 1: input projection + positional embedding ----------
__global__ void proj_kernel(const float* __restrict__ x,
                            const float* __restrict__ Wproj,
                            const float* __restrict__ bproj,
                            const float* __restrict__ pos)
{
    int idx = blockIdx.x * blockDim.x + threadIdx.x;
    if (idx >= BB * DM * LL) return;
    int l = idx & (LL - 1);
    int d = (idx >> 12) & (DM - 1);
    int b = idx >> 21;
    const float* xb = x + (size_t)b * CINN * LL;
    float v = bproj[d];
    v = fmaf(Wproj[d * 3 + 0], xb[l], v);
    v = fmaf(Wproj[d * 3 + 1], xb[LL + l], v);
    v = fmaf(Wproj[d * 3 + 2], xb[2 * LL + l], v);
    v += pos[(size_t)l * DM + d];
    g_h[idx] = v;
}

// ---------------- kernel 2a: chunk remainders (state-only, packed f32x2) ------
// 8 lanes per (channel, chunk); u held in registers (no shuffles).
__global__ void scanA_kernel(int layer)
{
    int gtid = blockIdx.x * blockDim.x + threadIdx.x;
    int pair = gtid >> 3;
    int r    = gtid & 7;
    int ch    = pair / (NCH - 1);
    int chunk = pair % (NCH - 1);
    int d = ch & (DM - 1);

    int pbase = (layer * DM + d) * N2C + 4 * r;
    uint64_t wre2[2], wim2[2], nwim2[2];
#pragma unroll
    for (int p = 0; p < 2; p++) {
        float w0 = g_wre[pbase + 2 * p], w1 = g_wre[pbase + 2 * p + 1];
        float i0 = g_wim[pbase + 2 * p], i1 = g_wim[pbase + 2 * p + 1];
        PK2(wre2[p], w0, w1);
        PK2(wim2[p], i0, i1);
        PK2(nwim2[p], -i0, -i1);
    }

    const float* u = g_h + (size_t)ch * LL + chunk * CH;
    uint64_t sre2[2] = {0ull, 0ull}, sim2[2] = {0ull, 0ull};

    for (int base = 0; base < CH; base += 32) {
        float4 f4[8];
        const float4* up = (const float4*)(u + base);
#pragma unroll
        for (int i = 0; i < 8; i++) f4[i] = up[i];
#pragma unroll
        for (int j = 0; j < 32; j++) {
            float4 q = f4[j >> 2];
            float uu = ((j & 3) == 0) ? q.x : ((j & 3) == 1) ? q.y
                     : ((j & 3) == 2) ? q.z : q.w;
            uint64_t uup;
            PK2(uup, uu, uu);
#pragma unroll
            for (int p = 0; p < 2; p++) {
                uint64_t t, rr, nre, nim;
                MUL2(t, wim2[p], sre2[p]);
                FMA2(rr, nwim2[p], sim2[p], uup);
                FMA2(nre, wre2[p], sre2[p], rr);
                FMA2(nim, wre2[p], sim2[p], t);
                sre2[p] = nre;
                sim2[p] = nim;
            }
        }
    }
    float* bnd = g_bnd + ((size_t)ch * NCH + chunk) * 64 + 8 * r;
#pragma unroll
    for (int p = 0; p < 2; p++) {
        float r0, r1, i0, i1;
        UPK2(r0, r1, sre2[p]);
        UPK2(i0, i1, sim2[p]);
        bnd[4 * p + 0] = r0;
        bnd[4 * p + 1] = i0;
        bnd[4 * p + 2] = r1;
        bnd[4 * p + 3] = i1;
    }
}

// ---------------- kernel 2c: output scan (packed) + GELU + fused transp/split -
__global__ void scanC_kernel(const float* __restrict__ Dskip, int layer)
{
    __shared__ float tile[32][65];
    __shared__ float sSre[32][32];
    __shared__ float sSim[32][32];
    int tid  = threadIdx.x;
    int wid  = tid >> 5;
    int lane = tid & 31;
    int g = lane >> 3;
    int r = lane & 7;
    int chunk = blockIdx.x;
    int chgrp = blockIdx.y;
    int chl = wid * 4 + g;
    int chn = chgrp * 32 + chl;
    int d = chn & (DM - 1);
    int b = chn >> 9;
    int d0 = (chgrp & 15) * 32;

    // ---- prologue: incoming state S_chunk for all 32 channels x 32 n
    {
#pragma unroll
        for (int it = 0; it < 4; it++) {
            int pid = tid + 256 * it;
            int pc = pid >> 5;
            int n  = pid & 31;
            int pch = chgrp * 32 + pc;
            int pd  = pch & (DM - 1);
            float wpre = g_wpre[(layer * DM + pd) * N2C + n];
            float wpim = g_wpim[(layer * DM + pd) * N2C + n];
            float Sre = 0.f, Sim = 0.f;
            const float* bnd = g_bnd + (size_t)pch * NCH * 64 + 2 * n;
            for (int k = 0; k < chunk; k++) {
                float rre = bnd[k * 64];
                float rim = bnd[k * 64 + 1];
                float nre = fmaf(wpre, Sre, fmaf(-wpim, Sim, rre));
                Sim = fmaf(wpre, Sim, fmaf(wpim, Sre, rim));
                Sre = nre;
            }
            sSre[pc][n] = Sre;
            sSim[pc][n] = Sim;
        }
        __syncthreads();
    }

    int pbase = (layer * DM + d) * N2C + 4 * r;
    uint64_t wre2[2], wim2[2], nwim2[2], cre2[2], ncim2[2];
#pragma unroll
    for (int p = 0; p < 2; p++) {
        float w0 = g_wre[pbase + 2 * p], w1 = g_wre[pbase + 2 * p + 1];
        float i0 = g_wim[pbase + 2 * p], i1 = g_wim[pbase + 2 * p + 1];
        float c0 = g_cre[pbase + 2 * p], c1 = g_cre[pbase + 2 * p + 1];
        float m0 = g_cim[pbase + 2 * p], m1 = g_cim[pbase + 2 * p + 1];
        PK2(wre2[p], w0, w1);
        PK2(wim2[p], i0, i1);
        PK2(nwim2[p], -i0, -i1);
        PK2(cre2[p], c0, c1);
        PK2(ncim2[p], -m0, -m1);
    }
    float dsk = Dskip[layer * DM + d];

    uint64_t sre2[2], sim2[2];
#pragma unroll
    for (int p = 0; p < 2; p++) {
        PK2(sre2[p], sSre[chl][4 * r + 2 * p], sSre[chl][4 * r + 2 * p + 1]);
        PK2(sim2[p], sSim[chl][4 * r + 2 * p], sSim[chl][4 * r + 2 * p + 1]);
    }
    __syncthreads();

    const float* u = g_h + (size_t)chn * LL + chunk * CH;
    size_t outrow0 = ((size_t)b * LL + chunk * CH) * DM + d0;

    for (int base = 0; base < CH; base += 32) {
        float uv[4];
#pragma unroll
        for (int k = 0; k < 4; k++) uv[k] = u[base + r + 8 * k];
        float yr[4] = {0.f, 0.f, 0.f, 0.f};
#pragma unroll
        for (int j = 0; j < 32; j++) {
            float uu = __shfl_sync(0xffffffffu, uv[j >> 3], (j & 7), 8);
            uint64_t uup;
            PK2(uup, uu, uu);
            uint64_t c2 = 0ull;
#pragma unroll
            for (int p = 0; p < 2; p++) {
                uint64_t t, rr, nre, nim;
                MUL2(t, wim2[p], sre2[p]);
                FMA2(rr, nwim2[p], sim2[p], uup);
                FMA2(nre, wre2[p], sre2[p], rr);
                FMA2(nim, wre2[p], sim2[p], t);
                sre2[p] = nre;
                sim2[p] = nim;
                FMA2(c2, cre2[p], nre, c2);
                FMA2(c2, ncim2[p], nim, c2);
            }
            float clo, chi;
            UPK2(clo, chi, c2);
            float c = clo + chi;
            c += __shfl_xor_sync(0xffffffffu, c, 4);
            c += __shfl_xor_sync(0xffffffffu, c, 2);
            c += __shfl_xor_sync(0xffffffffu, c, 1);
            if (r == (j & 7)) yr[j >> 3] = c;
        }
        int off = base & 32;
#pragma unroll
        for (int k = 0; k < 4; k++) {
            float v = fmaf(dsk, uv[k], yr[k]);
            float ge = 0.5f * v * (1.0f + erff(v * 0.70710678118654752f));
            tile[chl][off + r + 8 * k] = ge;
        }
        if (base & 32) {
            __syncthreads();
            int w0 = base - 32;
            int ll = tid >> 2;
            int dd0 = (tid & 3) * 8;
            __align__(16) __nv_bfloat16 hh[8];
#pragma unroll
            for (int i = 0; i < 8; i++)
                hh[i] = __float2bfloat16(tile[dd0 + i][ll]);
            size_t dst = outrow0 + (size_t)(w0 + ll) * DM + dd0;
            *(uint4*)(g_yth + dst) = *(uint4*)hh;
            __syncthreads();
        }
    }
}

// ---------------- kernel 3: HMMA 2-term bf16-split GEMM + GLU + residual ------
// D = Ah*Bh + Al*Bh  (W hi/lo corrections; Y-low term dropped, error averages out)
#define STAGE 49152
#define OFF_AH 0
#define OFF_AL 16384
#define OFF_BH 32768

__global__ void __launch_bounds__(256, 1)
gemm_mma_kernel(const float* __restrict__ bout, int layer)
{
    extern __shared__ char dsm[];
    uint32_t sb = smem_u32(dsm);

    const int tid  = threadIdx.x;
    const int wid  = tid >> 5;
    const int lane = tid & 31;
    const int wm   = wid >> 2;
    const int wn   = wid & 3;
    const int n0   = blockIdx.x * 128;
    const int m0   = blockIdx.y * 64;
    const int bb   = blockIdx.z;

    const __nv_bfloat16* Wh = g_wh + (size_t)layer * 2 * DM * DM;
    const __nv_bfloat16* Wl = g_wl + (size_t)layer * 2 * DM * DM;
    const __nv_bfloat16* Bh = g_yth + (size_t)bb * LL * DM;

    auto load_stage = [&](int c) {
        int buf = c % 3;
        int kb = c * 64;
        uint32_t base = sb + buf * STAGE;
#pragma unroll
        for (int i = 0; i < 4; i++) {
            int v = tid + (i << 8);
            int row = v >> 3;
            int seg = v & 7;
            uint32_t dsw = SW128((uint32_t)(row * 128 + seg * 16));
            int p = (row < 64) ? (m0 + row) : (448 + m0 + row);
            size_t ao = (size_t)p * DM + kb + seg * 8;
            cpa16(base + OFF_AH + dsw, Wh + ao);
            cpa16(base + OFF_AL + dsw, Wl + ao);
            size_t bo = (size_t)(n0 + row) * DM + kb + seg * 8;
            cpa16(base + OFF_BH + dsw, Bh + bo);
        }
        asm volatile("cp.async.commit_group;" ::: "memory");
    };

    float acc[4][4][4];
#pragma unroll
    for (int i = 0; i < 4; i++)
#pragma unroll
        for (int j = 0; j < 4; j++)
#pragma unroll
            for (int k = 0; k < 4; k++) acc[i][j][k] = 0.f;

    load_stage(0);
    load_stage(1);
    load_stage(2);

    for (int s = 0; s < 8; ++s) {
        if (s < 6)      asm volatile("cp.async.wait_group 2;" ::: "memory");
        else if (s == 6) asm volatile("cp.async.wait_group 1;" ::: "memory");
        else            asm volatile("cp.async.wait_group 0;" ::: "memory");
        __syncthreads();

        uint32_t base = sb + (s % 3) * STAGE;
#pragma unroll
        for (int k16 = 0; k16 < 4; ++k16) {
            uint32_t ah[4][4], al[4][4], bhf[4][2];
#pragma unroll
            for (int mf = 0; mf < 4; ++mf) {
                int rowbase = (mf < 2) ? (wm * 32 + mf * 16)
                                       : (64 + wm * 32 + (mf - 2) * 16);
                int row = rowbase + (lane & 15);
                uint32_t off = SW128((uint32_t)(row * 128 + k16 * 32 + ((lane >> 4) << 4)));
                LDMX4(ah[mf], base + OFF_AH + off);
                LDMX4(al[mf], base + OFF_AL + off);
            }
#pragma unroll
            for (int pr = 0; pr < 2; ++pr) {
                int row = wn * 32 + pr * 16 + (lane & 7) + ((lane >> 4) << 3);
                uint32_t off = SW128((uint32_t)(row * 128 + k16 * 32 + (((lane >> 3) & 1) << 4)));
                uint32_t t[4];
                LDMX4(t, base + OFF_BH + off);
                bhf[2 * pr][0] = t[0]; bhf[2 * pr][1] = t[1];
                bhf[2 * pr + 1][0] = t[2]; bhf[2 * pr + 1][1] = t[3];
            }
#pragma unroll
            for (int mf = 0; mf < 4; ++mf)
#pragma unroll
                for (int nf = 0; nf < 4; ++nf) {
                    MMA16816(acc[mf][nf], ah[mf], bhf[nf]);
                    MMA16816(acc[mf][nf], al[mf], bhf[nf]);
                }
        }
        __syncthreads();
        if (s < 5) load_stage(s + 3);
    }

    const float* bo = bout + layer * 2 * DM;
    int groupid = lane >> 2;
    int tg = lane & 3;
#pragma unroll
    for (int mf = 0; mf < 2; ++mf) {
#pragma unroll
        for (int rp = 0; rp < 2; ++rp) {
            int o = m0 + wm * 32 + mf * 16 + groupid + rp * 8;
            float b1 = bo[o];
            float b2 = bo[DM + o];
            float* H = g_h + ((size_t)bb * DM + o) * LL + n0 + wn * 32;
#pragma unroll
            for (int nf = 0; nf < 4; ++nf) {
                float a0 = acc[mf][nf][rp * 2 + 0] + b1;
                float a1 = acc[mf][nf][rp * 2 + 1] + b1;
                float g0 = acc[mf + 2][nf][rp * 2 + 0] + b2;
                float g1 = acc[mf + 2][nf][rp * 2 + 1] + b2;
                float z0 = a0 / (1.0f + expf(-g0));
                float z1 = a1 / (1.0f + expf(-g1));
                float2* ptr = (float2*)(H + nf * 8 + tg * 2);
                float2 h2 = *ptr;
                h2.x += z0;
                h2.y += z1;
                *ptr = h2;
            }
        }
    }
}

// ---------------- kernel 4: LayerNorm over channel dim (4-way split) ----------
__global__ void ln_kernel(const float* __restrict__ ln_g,
                          const float* __restrict__ ln_b, int layer)
{
    __shared__ float sS[4][64];
    __shared__ float sS2[4][64];
    __shared__ float sMu[64];
    __shared__ float sRs[64];
    int b  = blockIdx.y;
    int l0 = blockIdx.x * 64;
    int tid = threadIdx.x;
    int ll  = tid & 63;
    int grp = tid >> 6;
    float* H = g_h + (size_t)b * DM * LL + (size_t)grp * 128 * LL + l0 + ll;
    float s = 0.f, s2 = 0.f;
#pragma unroll 8
    for (int d = 0; d < 128; d++) {
        float v = H[(size_t)d * LL];
        s += v;
        s2 = fmaf(v, v, s2);
    }
    sS[grp][ll] = s;
    sS2[grp][ll] = s2;
    __syncthreads();
    if (tid < 64) {
        float st  = sS[0][tid] + sS[1][tid] + sS[2][tid] + sS[3][tid];
        float st2 = sS2[0][tid] + sS2[1][tid] + sS2[2][tid] + sS2[3][tid];
        float mu  = st * (1.0f / DM);
        float var = st2 * (1.0f / DM) - mu * mu;
        sMu[tid] = mu;
        sRs[tid] = rsqrtf(var + 1e-5f);
    }
    __syncthreads();
    float mu = sMu[ll];
    float rs = sRs[ll];
    const float* gv = ln_g + layer * DM + grp * 128;
    const float* bv = ln_b + layer * DM + grp * 128;
#pragma unroll 8
    for (int d = 0; d < 128; d++) {
        float v = H[(size_t)d * LL];
        H[(size_t)d * LL] = (v - mu) * rs * gv[d] + bv[d];
    }
}

// ---------------- kernel 5: mean over L ---------------------------------------
__global__ void mean_kernel()
{
    int ch = blockIdx.x;
    const float* H = g_h + (size_t)ch * LL;
    float s = 0.f;
    for (int l = threadIdx.x; l < LL; l += 128) s += H[l];
    __shared__ float sm[128];
    sm[threadIdx.x] = s;
    __syncthreads();
    for (int o = 64; o > 0; o >>= 1) {
        if (threadIdx.x < o) sm[threadIdx.x] += sm[threadIdx.x + o];
        __syncthreads();
    }
    if (threadIdx.x == 0) g_hbar[ch] = sm[0] * (1.0f / LL);
}

// ---------------- kernel 6: stats head + output layout ------------------------
__global__ void stats_kernel(const float* __restrict__ Wstats,
                             const float* __restrict__ bstats,
                             float* __restrict__ out)
{
    int idx = blockIdx.x * blockDim.x + threadIdx.x;
    if (idx >= BB * 2 * LAT) return;
    int b = idx / (2 * LAT);
    int o = idx % (2 * LAT);
    const float* hb = g_hbar + b * DM;
    const float* w  = Wstats + (size_t)o * DM;
    float s = bstats[o];
#pragma unroll 8
    for (int d = 0; d < DM; d++) s = fmaf(hb[d], w[d], s);
    int pos = (o < LAT) ? (b * LAT + o) : (BB * LAT + b * LAT + (o - LAT));
    out[pos] = s;
}

// ---------------- launch ------------------------------------------------------
extern "C" void kernel_launch(void* const* d_in, const int* in_sizes, int n_in,
                              void* d_out, int out_size)
{
    const float* x          = (const float*)d_in[0];
    const float* Wproj      = (const float*)d_in[1];
    const float* bproj      = (const float*)d_in[2];
    const float* pos        = (const float*)d_in[3];
    const float* log_dt     = (const float*)d_in[4];
    const float* log_A_real = (const float*)d_in[5];
    const float* A_imag     = (const float*)d_in[6];
    const float* C_re       = (const float*)d_in[7];
    const float* C_im       = (const float*)d_in[8];
    const float* Dskip      = (const float*)d_in[9];
    const float* Wout       = (const float*)d_in[10];
    const float* bout       = (const float*)d_in[11];
    const float* ln_g       = (const float*)d_in[12];
    const float* ln_b       = (const float*)d_in[13];
    const float* Wstats     = (const float*)d_in[14];
    const float* bstats     = (const float*)d_in[15];
    float* out = (float*)d_out;

    const int gemm_smem = 3 * STAGE;   // 144 KB
    cudaFuncSetAttribute(gemm_mma_kernel,
                         cudaFuncAttributeMaxDynamicSharedMemorySize, gemm_smem);

    precompute_kernel<<<(NLAY * DM * N2C) / 256, 256>>>(log_dt, log_A_real, A_imag, C_re, C_im);
    wsplit_kernel<<<(NLAY * 2 * DM * DM) / 256, 256>>>(Wout);
    proj_kernel<<<(BB * DM * LL) / 256, 256>>>(x, Wproj, bproj, pos);

    for (int layer = 0; layer < NLAY; ++layer) {
        scanA_kernel<<<(BB * DM * (NCH - 1) * 8) / 256, 256>>>(layer);
        scanC_kernel<<<dim3(NCH, (BB * DM) / 32), 256>>>(Dskip, layer);
        dim3 ggrid(LL / 128, DM / 64, BB);
        gemm_mma_kernel<<<ggrid, 256, gemm_smem>>>(bout, layer);
        dim3 lgrid(LL / 64, BB);
        ln_kernel<<<lgrid, 256>>>(ln_g, ln_b, layer);
    }

    mean_kernel<<<BB * DM, 128>>>();
    stats_kernel<<<(BB * 2 * LAT + 255) / 256, 256>>>(Wstats, bstats, out);
}

// round 14
// speedup vs baseline: 2.4217x; 1.2264x over previous
#include <cuda_runtime.h>
#include <cuda_bf16.h>
#include <math.h>
#include <stdint.h>

#define BB 8
#define CINN 3
#define DM 512
#define N2C 32
#define NLAY 4
#define LL 4096
#define LAT 256
#define NCH 16      // chunks per sequence
#define CH 256      // chunk length

// ---------------- scratch (device globals; no allocation allowed) -------------
__device__ float g_h[BB * DM * LL];              // activations [b][d][l]
__device__ __nv_bfloat16 g_yth[BB * LL * DM];    // Y^T hi  [b][l][d]
__device__ __nv_bfloat16 g_wh[NLAY * 2 * DM * DM];
__device__ __nv_bfloat16 g_wl[NLAY * 2 * DM * DM];
__device__ float g_wre[NLAY * DM * N2C];
__device__ float g_wim[NLAY * DM * N2C];
__device__ float g_cre[NLAY * DM * N2C];
__device__ float g_cim[NLAY * DM * N2C];
__device__ float g_wpre[NLAY * DM * N2C];        // w^CH real
__device__ float g_wpim[NLAY * DM * N2C];        // w^CH imag
__device__ float g_bnd[BB * DM * NCH * N2C * 2]; // chunk remainders r_c
__device__ float g_lnsum[BB * LL * 2];           // per (b,l): sum, sumsq of h
__device__ float g_hbar[BB * DM];

// ---------------- helpers -----------------------------------------------------
__device__ __forceinline__ uint32_t smem_u32(const void* p) {
    uint32_t a;
    asm("{ .reg .u64 t; cvta.to.shared.u64 t, %1; cvt.u32.u64 %0, t; }" : "=r"(a) : "l"(p));
    return a;
}
#define SW128(o) ((o) ^ (((o) >> 3) & 0x70))

#define LDMX4(r, addr) \
    asm volatile("ldmatrix.sync.aligned.m8n8.x4.shared.b16 {%0,%1,%2,%3}, [%4];" \
        : "=r"((r)[0]), "=r"((r)[1]), "=r"((r)[2]), "=r"((r)[3]) : "r"(addr))

#define MMA16816(c, a, b) \
    asm volatile("mma.sync.aligned.m16n8k16.row.col.f32.bf16.bf16.f32 " \
        "{%0,%1,%2,%3}, {%4,%5,%6,%7}, {%8,%9}, {%0,%1,%2,%3};" \
        : "+f"((c)[0]), "+f"((c)[1]), "+f"((c)[2]), "+f"((c)[3]) \
        : "r"((a)[0]), "r"((a)[1]), "r"((a)[2]), "r"((a)[3]), \
          "r"((b)[0]), "r"((b)[1]))

__device__ __forceinline__ void cpa16(uint32_t dst, const void* src) {
    asm volatile("cp.async.cg.shared.global [%0], [%1], 16;" :: "r"(dst), "l"(src));
}

// ---- packed fp32x2 (Blackwell FFMA2 path) ----
#define PK2(d, a, b) \
    asm("mov.b64 %0, {%1, %2};" : "=l"(d) : "r"(__float_as_uint(a)), "r"(__float_as_uint(b)))
#define UPK2(a, b, d) \
    { uint32_t _x, _y; asm("mov.b64 {%0, %1}, %2;" : "=r"(_x), "=r"(_y) : "l"(d)); \
      (a) = __uint_as_float(_x); (b) = __uint_as_float(_y); }
#define FMA2(d, a, b, c) \
    asm("fma.rn.f32x2 %0, %1, %2, %3;" : "=l"(d) : "l"(a), "l"(b), "l"(c))
#define MUL2(d, a, b) \
    asm("mul.rn.f32x2 %0, %1, %2;" : "=l"(d) : "l"(a), "l"(b))

// ---------------- kernel 0: per-layer SSM parameter precompute ----------------
__global__ void precompute_kernel(const float* __restrict__ log_dt,
                                  const float* __restrict__ log_A_real,
                                  const float* __restrict__ A_imag,
                                  const float* __restrict__ C_re,
                                  const float* __restrict__ C_im)
{
    int idx = blockIdx.x * blockDim.x + threadIdx.x;
    if (idx >= NLAY * DM * N2C) return;
    int hd = idx / N2C;
    float dt  = expf(log_dt[hd]);
    float are = -expf(log_A_real[idx]);
    float aim = A_imag[idx];
    float dre = are * dt;
    float dim = aim * dt;
    float er  = expf(dre);
    float wre = er * cosf(dim);
    float wim = er * sinf(dim);
    float Ere = wre - 1.0f;
    float Eim = wim;
    float inv = 1.0f / (are * are + aim * aim);
    float fre = (Ere * are + Eim * aim) * inv;
    float fim = (Eim * are - Ere * aim) * inv;
    float crr = C_re[idx], cii = C_im[idx];
    g_wre[idx] = wre;
    g_wim[idx] = wim;
    g_cre[idx] = 2.0f * (crr * fre - cii * fim);
    g_cim[idx] = 2.0f * (crr * fim + cii * fre);
    float pr = expf((float)CH * dre);
    g_wpre[idx] = pr * cosf((float)CH * dim);
    g_wpim[idx] = pr * sinf((float)CH * dim);
}

// ---------------- kernel 0b: bf16-split Wout ----------------------------------
__global__ void wsplit_kernel(const float* __restrict__ Wout)
{
    int idx = blockIdx.x * blockDim.x + threadIdx.x;
    if (idx >= NLAY * 2 * DM * DM) return;
    float v = Wout[idx];
    __nv_bfloat16 h = __float2bfloat16(v);
    g_wh[idx] = h;
    g_wl[idx] = __float2bfloat16(v - __bfloat162float(h));
}

// ---------------- kernel 1: input projection + positional embedding ----------
__global__ void proj_kernel(const float* __restrict__ x,
                            const float* __restrict__ Wproj,
                            const float* __restrict__ bproj,
                            const float* __restrict__ pos)
{
    int idx = blockIdx.x * blockDim.x + threadIdx.x;
    if (idx >= BB * DM * LL) return;
    int l = idx & (LL - 1);
    int d = (idx >> 12) & (DM - 1);
    int b = idx >> 21;
    const float* xb = x + (size_t)b * CINN * LL;
    float v = bproj[d];
    v = fmaf(Wproj[d * 3 + 0], xb[l], v);
    v = fmaf(Wproj[d * 3 + 1], xb[LL + l], v);
    v = fmaf(Wproj[d * 3 + 2], xb[2 * LL + l], v);
    v += pos[(size_t)l * DM + d];
    g_h[idx] = v;
}

// ---------------- kernel 2a: chunk remainders, 4-step-blocked recurrence ------
// s <- w^4 s + (w^3 u1 + w^2 u2 + w u3 + u4); packed f32x2 over state pairs.
// Also zeroes g_lnsum for this layer's GEMM epilogue statistics.
__global__ void scanA_kernel(int layer)
{
    int gtid = blockIdx.x * blockDim.x + threadIdx.x;
    if (gtid < BB * LL * 2) g_lnsum[gtid] = 0.f;

    int pair = gtid >> 3;
    int r    = gtid & 7;
    int ch    = pair / (NCH - 1);
    int chunk = pair % (NCH - 1);
    int d = ch & (DM - 1);

    int pbase = (layer * DM + d) * N2C + 4 * r;
    // scalar powers w^1..w^4 per state, then pack pairs
    float a1r[4], a1i[4], a2r[4], a2i[4], a3r[4], a3i[4], a4r[4], a4i[4];
#pragma unroll
    for (int q = 0; q < 4; q++) {
        a1r[q] = g_wre[pbase + q];
        a1i[q] = g_wim[pbase + q];
        a2r[q] = a1r[q] * a1r[q] - a1i[q] * a1i[q];
        a2i[q] = 2.0f * a1r[q] * a1i[q];
        a3r[q] = a2r[q] * a1r[q] - a2i[q] * a1i[q];
        a3i[q] = a2r[q] * a1i[q] + a2i[q] * a1r[q];
        a4r[q] = a2r[q] * a2r[q] - a2i[q] * a2i[q];
        a4i[q] = 2.0f * a2r[q] * a2i[q];
    }
    uint64_t w1re2[2], w1im2[2], w2re2[2], w2im2[2], w3re2[2], w3im2[2];
    uint64_t w4re2[2], w4im2[2], nw4im2[2];
#pragma unroll
    for (int p = 0; p < 2; p++) {
        PK2(w1re2[p], a1r[2 * p], a1r[2 * p + 1]);
        PK2(w1im2[p], a1i[2 * p], a1i[2 * p + 1]);
        PK2(w2re2[p], a2r[2 * p], a2r[2 * p + 1]);
        PK2(w2im2[p], a2i[2 * p], a2i[2 * p + 1]);
        PK2(w3re2[p], a3r[2 * p], a3r[2 * p + 1]);
        PK2(w3im2[p], a3i[2 * p], a3i[2 * p + 1]);
        PK2(w4re2[p], a4r[2 * p], a4r[2 * p + 1]);
        PK2(w4im2[p], a4i[2 * p], a4i[2 * p + 1]);
        PK2(nw4im2[p], -a4i[2 * p], -a4i[2 * p + 1]);
    }

    const float* u = g_h + (size_t)ch * LL + chunk * CH;
    uint64_t sre2[2] = {0ull, 0ull}, sim2[2] = {0ull, 0ull};

    for (int base = 0; base < CH; base += 32) {
        float4 f4[8];
        const float4* up = (const float4*)(u + base);
#pragma unroll
        for (int i = 0; i < 8; i++) f4[i] = up[i];
#pragma unroll
        for (int i = 0; i < 8; i++) {
            float4 q = f4[i];
            uint64_t ux, uy, uz, uw;
            PK2(ux, q.x, q.x);
            PK2(uy, q.y, q.y);
            PK2(uz, q.z, q.z);
            PK2(uw, q.w, q.w);
#pragma unroll
            for (int p = 0; p < 2; p++) {
                uint64_t vre, vim, rr, xx, nre, nim;
                FMA2(vre, w3re2[p], ux, uw);
                FMA2(vre, w2re2[p], uy, vre);
                FMA2(vre, w1re2[p], uz, vre);
                MUL2(vim, w3im2[p], ux);
                FMA2(vim, w2im2[p], uy, vim);
                FMA2(vim, w1im2[p], uz, vim);
                FMA2(xx, w4im2[p], sre2[p], vim);
                FMA2(rr, nw4im2[p], sim2[p], vre);
                FMA2(nre, w4re2[p], sre2[p], rr);
                FMA2(nim, w4re2[p], sim2[p], xx);
                sre2[p] = nre;
                sim2[p] = nim;
            }
        }
    }
    float* bnd = g_bnd + ((size_t)ch * NCH + chunk) * 64 + 8 * r;
#pragma unroll
    for (int p = 0; p < 2; p++) {
        float r0, r1, i0, i1;
        UPK2(r0, r1, sre2[p]);
        UPK2(i0, i1, sim2[p]);
        bnd[4 * p + 0] = r0;
        bnd[4 * p + 1] = i0;
        bnd[4 * p + 2] = r1;
        bnd[4 * p + 3] = i1;
    }
}

// ---------------- kernel 2c: output scan (packed) + GELU + fused transp/split -
__global__ void scanC_kernel(const float* __restrict__ Dskip, int layer)
{
    __shared__ float tile[32][65];
    __shared__ float sSre[32][32];
    __shared__ float sSim[32][32];
    int tid  = threadIdx.x;
    int wid  = tid >> 5;
    int lane = tid & 31;
    int g = lane >> 3;
    int r = lane & 7;
    int chunk = blockIdx.x;
    int chgrp = blockIdx.y;
    int chl = wid * 4 + g;
    int chn = chgrp * 32 + chl;
    int d = chn & (DM - 1);
    int b = chn >> 9;
    int d0 = (chgrp & 15) * 32;

    // ---- prologue: incoming state S_chunk for all 32 channels x 32 n
    {
#pragma unroll
        for (int it = 0; it < 4; it++) {
            int pid = tid + 256 * it;
            int pc = pid >> 5;
            int n  = pid & 31;
            int pch = chgrp * 32 + pc;
            int pd  = pch & (DM - 1);
            float wpre = g_wpre[(layer * DM + pd) * N2C + n];
            float wpim = g_wpim[(layer * DM + pd) * N2C + n];
            float Sre = 0.f, Sim = 0.f;
            const float* bnd = g_bnd + (size_t)pch * NCH * 64 + 2 * n;
            for (int k = 0; k < chunk; k++) {
                float rre = bnd[k * 64];
                float rim = bnd[k * 64 + 1];
                float nre = fmaf(wpre, Sre, fmaf(-wpim, Sim, rre));
                Sim = fmaf(wpre, Sim, fmaf(wpim, Sre, rim));
                Sre = nre;
            }
            sSre[pc][n] = Sre;
            sSim[pc][n] = Sim;
        }
        __syncthreads();
    }

    int pbase = (layer * DM + d) * N2C + 4 * r;
    uint64_t wre2[2], wim2[2], nwim2[2], cre2[2], ncim2[2];
#pragma unroll
    for (int p = 0; p < 2; p++) {
        float w0 = g_wre[pbase + 2 * p], w1 = g_wre[pbase + 2 * p + 1];
        float i0 = g_wim[pbase + 2 * p], i1 = g_wim[pbase + 2 * p + 1];
        float c0 = g_cre[pbase + 2 * p], c1 = g_cre[pbase + 2 * p + 1];
        float m0 = g_cim[pbase + 2 * p], m1 = g_cim[pbase + 2 * p + 1];
        PK2(wre2[p], w0, w1);
        PK2(wim2[p], i0, i1);
        PK2(nwim2[p], -i0, -i1);
        PK2(cre2[p], c0, c1);
        PK2(ncim2[p], -m0, -m1);
    }
    float dsk = Dskip[layer * DM + d];

    uint64_t sre2[2], sim2[2];
#pragma unroll
    for (int p = 0; p < 2; p++) {
        PK2(sre2[p], sSre[chl][4 * r + 2 * p], sSre[chl][4 * r + 2 * p + 1]);
        PK2(sim2[p], sSim[chl][4 * r + 2 * p], sSim[chl][4 * r + 2 * p + 1]);
    }
    __syncthreads();

    const float* u = g_h + (size_t)chn * LL + chunk * CH;
    size_t outrow0 = ((size_t)b * LL + chunk * CH) * DM + d0;

    for (int base = 0; base < CH; base += 32) {
        float uv[4];
#pragma unroll
        for (int k = 0; k < 4; k++) uv[k] = u[base + r + 8 * k];
        float yr[4] = {0.f, 0.f, 0.f, 0.f};
#pragma unroll
        for (int j = 0; j < 32; j++) {
            float uu = __shfl_sync(0xffffffffu, uv[j >> 3], (j & 7), 8);
            uint64_t uup;
            PK2(uup, uu, uu);
            uint64_t c2 = 0ull;
#pragma unroll
            for (int p = 0; p < 2; p++) {
                uint64_t t, rr, nre, nim;
                MUL2(t, wim2[p], sre2[p]);
                FMA2(rr, nwim2[p], sim2[p], uup);
                FMA2(nre, wre2[p], sre2[p], rr);
                FMA2(nim, wre2[p], sim2[p], t);
                sre2[p] = nre;
                sim2[p] = nim;
                FMA2(c2, cre2[p], nre, c2);
                FMA2(c2, ncim2[p], nim, c2);
            }
            float clo, chi;
            UPK2(clo, chi, c2);
            float c = clo + chi;
            c += __shfl_xor_sync(0xffffffffu, c, 4);
            c += __shfl_xor_sync(0xffffffffu, c, 2);
            c += __shfl_xor_sync(0xffffffffu, c, 1);
            if (r == (j & 7)) yr[j >> 3] = c;
        }
        int off = base & 32;
#pragma unroll
        for (int k = 0; k < 4; k++) {
            float v = fmaf(dsk, uv[k], yr[k]);
            float ge = 0.5f * v * (1.0f + erff(v * 0.70710678118654752f));
            tile[chl][off + r + 8 * k] = ge;
        }
        if (base & 32) {
            __syncthreads();
            int w0 = base - 32;
            int ll = tid >> 2;
            int dd0 = (tid & 3) * 8;
            __align__(16) __nv_bfloat16 hh[8];
#pragma unroll
            for (int i = 0; i < 8; i++)
                hh[i] = __float2bfloat16(tile[dd0 + i][ll]);
            size_t dst = outrow0 + (size_t)(w0 + ll) * DM + dd0;
            *(uint4*)(g_yth + dst) = *(uint4*)hh;
            __syncthreads();
        }
    }
}

// ---------------- kernel 3: HMMA 2-term GEMM + GLU + residual + LN stats ------
#define STAGE 49152
#define OFF_AH 0
#define OFF_AL 16384
#define OFF_BH 32768

__global__ void __launch_bounds__(256, 2)
gemm_mma_kernel(const float* __restrict__ bout, int layer)
{
    extern __shared__ char dsm[];
    uint32_t sb = smem_u32(dsm);

    const int tid  = threadIdx.x;
    const int wid  = tid >> 5;
    const int lane = tid & 31;
    const int wm   = wid >> 2;
    const int wn   = wid & 3;
    const int n0   = blockIdx.x * 128;
    const int m0   = blockIdx.y * 64;
    const int bb   = blockIdx.z;

    const __nv_bfloat16* Wh = g_wh + (size_t)layer * 2 * DM * DM;
    const __nv_bfloat16* Wl = g_wl + (size_t)layer * 2 * DM * DM;
    const __nv_bfloat16* Bh = g_yth + (size_t)bb * LL * DM;

    auto load_stage = [&](int c) {
        int buf = c & 1;
        int kb = c * 64;
        uint32_t base = sb + buf * STAGE;
#pragma unroll
        for (int i = 0; i < 4; i++) {
            int v = tid + (i << 8);
            int row = v >> 3;
            int seg = v & 7;
            uint32_t dsw = SW128((uint32_t)(row * 128 + seg * 16));
            int p = (row < 64) ? (m0 + row) : (448 + m0 + row);
            size_t ao = (size_t)p * DM + kb + seg * 8;
            cpa16(base + OFF_AH + dsw, Wh + ao);
            cpa16(base + OFF_AL + dsw, Wl + ao);
            size_t bo = (size_t)(n0 + row) * DM + kb + seg * 8;
            cpa16(base + OFF_BH + dsw, Bh + bo);
        }
        asm volatile("cp.async.commit_group;" ::: "memory");
    };

    float acc[4][4][4];
#pragma unroll
    for (int i = 0; i < 4; i++)
#pragma unroll
        for (int j = 0; j < 4; j++)
#pragma unroll
            for (int k = 0; k < 4; k++) acc[i][j][k] = 0.f;

    load_stage(0);
    load_stage(1);

    for (int s = 0; s < 8; ++s) {
        if (s < 7) asm volatile("cp.async.wait_group 1;" ::: "memory");
        else       asm volatile("cp.async.wait_group 0;" ::: "memory");
        __syncthreads();

        uint32_t base = sb + (s & 1) * STAGE;
#pragma unroll
        for (int k16 = 0; k16 < 4; ++k16) {
            uint32_t ah[4][4], al[4][4], bhf[4][2];
#pragma unroll
            for (int mf = 0; mf < 4; ++mf) {
                int rowbase = (mf < 2) ? (wm * 32 + mf * 16)
                                       : (64 + wm * 32 + (mf - 2) * 16);
                int row = rowbase + (lane & 15);
                uint32_t off = SW128((uint32_t)(row * 128 + k16 * 32 + ((lane >> 4) << 4)));
                LDMX4(ah[mf], base + OFF_AH + off);
                LDMX4(al[mf], base + OFF_AL + off);
            }
#pragma unroll
            for (int pr = 0; pr < 2; ++pr) {
                int row = wn * 32 + pr * 16 + (lane & 7) + ((lane >> 4) << 3);
                uint32_t off = SW128((uint32_t)(row * 128 + k16 * 32 + (((lane >> 3) & 1) << 4)));
                uint32_t t[4];
                LDMX4(t, base + OFF_BH + off);
                bhf[2 * pr][0] = t[0]; bhf[2 * pr][1] = t[1];
                bhf[2 * pr + 1][0] = t[2]; bhf[2 * pr + 1][1] = t[3];
            }
#pragma unroll
            for (int mf = 0; mf < 4; ++mf)
#pragma unroll
                for (int nf = 0; nf < 4; ++nf) {
                    MMA16816(acc[mf][nf], ah[mf], bhf[nf]);
                    MMA16816(acc[mf][nf], al[mf], bhf[nf]);
                }
        }
        __syncthreads();
        if (s < 6) load_stage(s + 2);
    }

    const float* bo = bout + layer * 2 * DM;
    int groupid = lane >> 2;
    int tg = lane & 3;
    float sacc[4][2], s2acc[4][2];
#pragma unroll
    for (int nf = 0; nf < 4; nf++) {
        sacc[nf][0] = 0.f; sacc[nf][1] = 0.f;
        s2acc[nf][0] = 0.f; s2acc[nf][1] = 0.f;
    }
#pragma unroll
    for (int mf = 0; mf < 2; ++mf) {
#pragma unroll
        for (int rp = 0; rp < 2; ++rp) {
            int o = m0 + wm * 32 + mf * 16 + groupid + rp * 8;
            float b1 = bo[o];
            float b2 = bo[DM + o];
            float* H = g_h + ((size_t)bb * DM + o) * LL + n0 + wn * 32;
#pragma unroll
            for (int nf = 0; nf < 4; ++nf) {
                float a0 = acc[mf][nf][rp * 2 + 0] + b1;
                float a1 = acc[mf][nf][rp * 2 + 1] + b1;
                float g0 = acc[mf + 2][nf][rp * 2 + 0] + b2;
                float g1 = acc[mf + 2][nf][rp * 2 + 1] + b2;
                float z0 = a0 / (1.0f + expf(-g0));
                float z1 = a1 / (1.0f + expf(-g1));
                float2* ptr = (float2*)(H + nf * 8 + tg * 2);
                float2 h2 = *ptr;
                h2.x += z0;
                h2.y += z1;
                *ptr = h2;
                sacc[nf][0] += h2.x;
                s2acc[nf][0] = fmaf(h2.x, h2.x, s2acc[nf][0]);
                sacc[nf][1] += h2.y;
                s2acc[nf][1] = fmaf(h2.y, h2.y, s2acc[nf][1]);
            }
        }
    }
    // reduce over the 8 groupid lanes (o-dimension) and accumulate LN stats
#pragma unroll
    for (int nf = 0; nf < 4; ++nf) {
#pragma unroll
        for (int q = 0; q < 2; ++q) {
            float s = sacc[nf][q], s2 = s2acc[nf][q];
            s  += __shfl_xor_sync(0xffffffffu, s, 4);
            s  += __shfl_xor_sync(0xffffffffu, s, 8);
            s  += __shfl_xor_sync(0xffffffffu, s, 16);
            s2 += __shfl_xor_sync(0xffffffffu, s2, 4);
            s2 += __shfl_xor_sync(0xffffffffu, s2, 8);
            s2 += __shfl_xor_sync(0xffffffffu, s2, 16);
            if (groupid == 0) {
                int l = n0 + wn * 32 + nf * 8 + tg * 2 + q;
                atomicAdd(&g_lnsum[((size_t)bb * LL + l) * 2 + 0], s);
                atomicAdd(&g_lnsum[((size_t)bb * LL + l) * 2 + 1], s2);
            }
        }
    }
}

// ---------------- kernel 4: LayerNorm normalize (single pass, stats from GEMM)
__global__ void ln_kernel(const float* __restrict__ ln_g,
                          const float* __restrict__ ln_b, int layer)
{
    int b  = blockIdx.y;
    int l0 = blockIdx.x * 64;
    int tid = threadIdx.x;
    int ll  = tid & 63;
    int grp = tid >> 6;
    int l = l0 + ll;
    float sum = g_lnsum[((size_t)b * LL + l) * 2 + 0];
    float s2  = g_lnsum[((size_t)b * LL + l) * 2 + 1];
    float mu  = sum * (1.0f / DM);
    float var = s2 * (1.0f / DM) - mu * mu;
    float rs  = rsqrtf(var + 1e-5f);
    float* H = g_h + (size_t)b * DM * LL + (size_t)grp * 128 * LL + l;
    const float* gv = ln_g + layer * DM + grp * 128;
    const float* bv = ln_b + layer * DM + grp * 128;
#pragma unroll 8
    for (int d = 0; d < 128; d++) {
        float v = H[(size_t)d * LL];
        H[(size_t)d * LL] = (v - mu) * rs * gv[d] + bv[d];
    }
}

// ---------------- kernel 5: mean over L ---------------------------------------
__global__ void mean_kernel()
{
    int ch = blockIdx.x;
    const float* H = g_h + (size_t)ch * LL;
    float s = 0.f;
    for (int l = threadIdx.x; l < LL; l += 128) s += H[l];
    __shared__ float sm[128];
    sm[threadIdx.x] = s;
    __syncthreads();
    for (int o = 64; o > 0; o >>= 1) {
        if (threadIdx.x < o) sm[threadIdx.x] += sm[threadIdx.x + o];
        __syncthreads();
    }
    if (threadIdx.x == 0) g_hbar[ch] = sm[0] * (1.0f / LL);
}

// ---------------- kernel 6: stats head + output layout ------------------------
__global__ void stats_kernel(const float* __restrict__ Wstats,
                             const float* __restrict__ bstats,
                             float* __restrict__ out)
{
    int idx = blockIdx.x * blockDim.x + threadIdx.x;
    if (idx >= BB * 2 * LAT) return;
    int b = idx / (2 * LAT);
    int o = idx % (2 * LAT);
    const float* hb = g_hbar + b * DM;
    const float* w  = Wstats + (size_t)o * DM;
    float s = bstats[o];
#pragma unroll 8
    for (int d = 0; d < DM; d++) s = fmaf(hb[d], w[d], s);
    int pos = (o < LAT) ? (b * LAT + o) : (BB * LAT + b * LAT + (o - LAT));
    out[pos] = s;
}

// ---------------- launch ------------------------------------------------------
extern "C" void kernel_launch(void* const* d_in, const int* in_sizes, int n_in,
                              void* d_out, int out_size)
{
    const float* x          = (const float*)d_in[0];
    const float* Wproj      = (const float*)d_in[1];
    const float* bproj      = (const float*)d_in[2];
    const float* pos        = (const float*)d_in[3];
    const float* log_dt     = (const float*)d_in[4];
    const float* log_A_real = (const float*)d_in[5];
    const float* A_imag     = (const float*)d_in[6];
    const float* C_re       = (const float*)d_in[7];
    const float* C_im       = (const float*)d_in[8];
    const float* Dskip      = (const float*)d_in[9];
    const float* Wout       = (const float*)d_in[10];
    const float* bout       = (const float*)d_in[11];
    const float* ln_g       = (const float*)d_in[12];
    const float* ln_b       = (const float*)d_in[13];
    const float* Wstats     = (const float*)d_in[14];
    const float* bstats     = (const float*)d_in[15];
    float* out = (float*)d_out;

    const int gemm_smem = 2 * STAGE;   // 96 KB -> 2 CTAs/SM
    cudaFuncSetAttribute(gemm_mma_kernel,
                         cudaFuncAttributeMaxDynamicSharedMemorySize, gemm_smem);

    precompute_kernel<<<(NLAY * DM * N2C) / 256, 256>>>(log_dt, log_A_real, A_imag, C_re, C_im);
    wsplit_kernel<<<(NLAY * 2 * DM * DM) / 256, 256>>>(Wout);
    proj_kernel<<<(BB * DM * LL) / 256, 256>>>(x, Wproj, bproj, pos);

    for (int layer = 0; layer < NLAY; ++layer) {
        scanA_kernel<<<(BB * DM * (NCH - 1) * 8) / 256, 256>>>(layer);
        scanC_kernel<<<dim3(NCH, (BB * DM) / 32), 256>>>(Dskip, layer);
        dim3 ggrid(LL / 128, DM / 64, BB);
        gemm_mma_kernel<<<ggrid, 256, gemm_smem>>>(bout, layer);
        dim3 lgrid(LL / 64, BB);
        ln_kernel<<<lgrid, 256>>>(ln_g, ln_b, layer);
    }

    mean_kernel<<<BB * DM, 128>>>();
    stats_kernel<<<(BB * 2 * LAT + 255) / 256, 256>>>(Wstats, bstats, out);
}